// round 8
// baseline (speedup 1.0000x reference)
#include <cuda_runtime.h>
#include <cstdint>

#define B_  32
#define C_  256
#define H_  64
#define W_  64
#define HW_ 4096
#define EPS 1e-5f

// ---------------- scratch (device globals: no allocations allowed) ----------
__device__ float g_edge[(size_t)B_ * C_ * HW_];   // relu(bn(dwconv(x)))
__device__ float g_t1 [(size_t)B_ * C_ * HW_];    // bn1(fusion conv)
__device__ float g_t2 [(size_t)B_ * C_ * HW_];    // deform dwconv output
__device__ float g_avg[B_ * C_];
__device__ float g_att[B_ * C_];

// ---------------- 2) SE MLP -------------------------------------------------
__global__ __launch_bounds__(512) void se_kernel(const float* __restrict__ fc1_w,
                                                 const float* __restrict__ fc2_w) {
    __shared__ float sa[B_ * C_];
    __shared__ float shh[B_ * 16];
    int tid = threadIdx.x;
    for (int i = tid; i < B_ * C_; i += 512) sa[i] = g_avg[i];
    __syncthreads();
    {
        int b = tid >> 4, j = tid & 15;
        float s = 0.f;
        #pragma unroll 8
        for (int c = 0; c < C_; c++) s += sa[b * C_ + c] * fc1_w[j * C_ + c];
        shh[b * 16 + j] = fmaxf(s, 0.f);
    }
    __syncthreads();
    for (int idx = tid; idx < B_ * C_; idx += 512) {
        int b = idx >> 8, o = idx & 255;
        float s = 0.f;
        #pragma unroll
        for (int j = 0; j < 16; j++) s += shh[b * 16 + j] * fc2_w[o * 16 + j];
        g_att[idx] = 1.0f / (1.0f + expf(-s));
    }
}

// ------- 3/5) depthwise 3x3, register rotation; optional BN+ReLU / mean -----
template<bool BNRELU, bool DOMEAN>
__global__ __launch_bounds__(256) void dwconv_kernel(const float* __restrict__ src,
                                                     const float* __restrict__ w9,
                                                     float* __restrict__ dst,
                                                     const float* __restrict__ gma,
                                                     const float* __restrict__ bta,
                                                     const float* __restrict__ mn,
                                                     const float* __restrict__ vr) {
    __shared__ float sh[66][67];
    __shared__ float ws[8];
    int plane = blockIdx.x;
    int c = plane & (C_ - 1);
    const float* sp = src + (size_t)plane * HW_;
    int tid = threadIdx.x;
    for (int idx = tid; idx < 66 * 66; idx += 256) {
        int r = idx / 66, cc = idx - r * 66;
        int yy = r - 1, xx = cc - 1;
        float v = 0.f;
        if (yy >= 0 && yy < H_ && xx >= 0 && xx < W_) v = sp[yy * W_ + xx];
        sh[r][cc] = v;
    }
    float w[9];
    #pragma unroll
    for (int i = 0; i < 9; i++) w[i] = w9[c * 9 + i];
    float inv = 1.f, add = 0.f;
    if (BNRELU) { inv = gma[c] * rsqrtf(vr[c] + EPS); add = bta[c] - mn[c] * inv; }
    __syncthreads();

    const int col = tid & 63;
    const int r0  = (tid >> 6) << 4;          // 4 strips of 16 rows
    float* dp = dst + (size_t)plane * HW_;

    float t0 = sh[r0][col],     t1 = sh[r0][col + 1],     t2 = sh[r0][col + 2];
    float m0 = sh[r0 + 1][col], m1 = sh[r0 + 1][col + 1], m2 = sh[r0 + 1][col + 2];
    float msum = 0.f;
    #pragma unroll
    for (int i = 0; i < 16; i++) {
        float b0 = sh[r0 + 2 + i][col];
        float b1 = sh[r0 + 2 + i][col + 1];
        float b2 = sh[r0 + 2 + i][col + 2];
        float s = w[0] * t0 + w[1] * t1 + w[2] * t2
                + w[3] * m0 + w[4] * m1 + w[5] * m2
                + w[6] * b0 + w[7] * b1 + w[8] * b2;
        if (DOMEAN) msum += m1;               // m1 == x[r0+i, col]
        if (BNRELU) s = fmaxf(s * inv + add, 0.f);
        dp[(r0 + i) * W_ + col] = s;
        t0 = m0; t1 = m1; t2 = m2;
        m0 = b0; m1 = b1; m2 = b2;
    }

    if (DOMEAN) {
        #pragma unroll
        for (int o = 16; o; o >>= 1) msum += __shfl_xor_sync(0xffffffffu, msum, o);
        if ((tid & 31) == 0) ws[tid >> 5] = msum;
        __syncthreads();
        if (tid == 0) {
            float t = 0.f;
            #pragma unroll
            for (int i = 0; i < 8; i++) t += ws[i];
            g_avg[plane] = t * (1.0f / HW_);
        }
    }
}

// =================== tf32 mma.sync GEMM (fragment-layout smem) ==============
__device__ __forceinline__ uint32_t f2tf32(float x) {
    uint32_t r;
    asm("cvt.rna.tf32.f32 %0, %1;" : "=r"(r) : "f"(x));
    return r;
}

__device__ __forceinline__ void mma_tf32_16x8x8(
    float& d0, float& d1, float& d2, float& d3,
    uint32_t a0, uint32_t a1, uint32_t a2, uint32_t a3,
    uint32_t b0, uint32_t b1) {
    asm volatile(
        "mma.sync.aligned.m16n8k8.row.col.f32.tf32.tf32.f32 "
        "{%0,%1,%2,%3}, {%4,%5,%6,%7}, {%8,%9}, {%0,%1,%2,%3};"
        : "+f"(d0), "+f"(d1), "+f"(d2), "+f"(d3)
        : "r"(a0), "r"(a1), "r"(a2), "r"(a3), "r"(b0), "r"(b1));
}

// swizzle for row in the [row][8] fragment store
__device__ __forceinline__ int rswz(int row) {
    return 2 * (((row >> 2) ^ row) & 3);
}

// Block tile: M=128 channels, N=128 pixels, K chunk 16; 8 warps (2M x 4N).
// Smem layout: [buf][k8blk][row][8] floats, k-pair interleaved + XOR swizzle:
//   logical k stored at slot ((k&3)*2 + (k>>2)) ^ rswz(row)
// so fragment pair (k=tig, k=tig+4) is one aligned LDS.64.
template<int KTOT, bool IS_G1>
__global__ __launch_bounds__(256, 2) void tgemm_kernel(
    const float* __restrict__ act,
    const float* __restrict__ wgt,
    const float* __restrict__ bias,
    const float* __restrict__ gma, const float* __restrict__ bta,
    const float* __restrict__ mnn, const float* __restrict__ vr,
    const float* __restrict__ xg,
    float* __restrict__ dst)
{
    __shared__ __align__(16) float Asf[2][2][128][8];
    __shared__ __align__(16) float Bsf[2][2][128][8];

    const int tid = threadIdx.x;
    const int wid = tid >> 5, lane = tid & 31;
    const int g = lane >> 2, tig = lane & 3;
    const int b  = blockIdx.z;
    const int o0 = blockIdx.y * 128;
    const int p0 = blockIdx.x * 128;
    const int warpM = (wid & 1) * 64;
    const int warpN = (wid >> 1) * 32;

    const float* actb = act    + (size_t)b * C_ * HW_;
    const float* edgb = g_edge + (size_t)b * C_ * HW_;
    const float* attb = g_att  + b * C_;

    // A staging: one row, one k8-block (8 consecutive k) per thread
    const int a_m  = tid & 127;
    const int a_k8 = tid >> 7;
    const int asw  = rswz(a_m);
    // B staging: one k row, 8 columns at stride 16
    const int b_kl = tid >> 4;            // 0..15 local k
    const int b_k8 = b_kl >> 3;
    const int b_kk = ((b_kl & 3) * 2) + ((b_kl & 7) >> 2);
    const int b_n0 = tid & 15;
    const int bsw  = rswz(b_n0);          // rswz(b_n0 + 16j) == rswz(b_n0)

    float acc[4][4][4];
    #pragma unroll
    for (int i = 0; i < 4; i++)
        #pragma unroll
        for (int j = 0; j < 4; j++)
            #pragma unroll
            for (int q = 0; q < 4; q++) acc[i][j][q] = 0.f;

    float4 ra0, ra1;
    float rbv[8];

    #define LOAD_CHUNK(K0)                                                       \
    {                                                                            \
        const float* ap = wgt + (size_t)(o0 + a_m) * KTOT + (K0) + a_k8 * 8;     \
        ra0 = *(const float4*)ap;                                                \
        ra1 = *(const float4*)(ap + 4);                                          \
        const int kg = (K0) + b_kl;                                              \
        if (IS_G1) {                                                             \
            if (kg < C_) {                                                       \
                const float* bp = actb + (size_t)kg * HW_ + p0 + b_n0;           \
                const float s = attb[kg];                                        \
                _Pragma("unroll")                                                \
                for (int j = 0; j < 8; j++) rbv[j] = bp[j * 16] * s;             \
            } else {                                                             \
                const float* bp = edgb + (size_t)(kg - C_) * HW_ + p0 + b_n0;    \
                _Pragma("unroll")                                                \
                for (int j = 0; j < 8; j++) rbv[j] = bp[j * 16];                 \
            }                                                                    \
        } else {                                                                 \
            const float* bp = actb + (size_t)kg * HW_ + p0 + b_n0;               \
            _Pragma("unroll")                                                    \
            for (int j = 0; j < 8; j++) rbv[j] = bp[j * 16];                     \
        }                                                                        \
    }

    #define STORE_CHUNK(BUF)                                                     \
    {                                                                            \
        float* da = &Asf[BUF][a_k8][a_m][0];                                     \
        da[0 ^ asw] = __uint_as_float(f2tf32(ra0.x));                            \
        da[2 ^ asw] = __uint_as_float(f2tf32(ra0.y));                            \
        da[4 ^ asw] = __uint_as_float(f2tf32(ra0.z));                            \
        da[6 ^ asw] = __uint_as_float(f2tf32(ra0.w));                            \
        da[1 ^ asw] = __uint_as_float(f2tf32(ra1.x));                            \
        da[3 ^ asw] = __uint_as_float(f2tf32(ra1.y));                            \
        da[5 ^ asw] = __uint_as_float(f2tf32(ra1.z));                            \
        da[7 ^ asw] = __uint_as_float(f2tf32(ra1.w));                            \
        _Pragma("unroll")                                                        \
        for (int j = 0; j < 8; j++)                                              \
            Bsf[BUF][b_k8][b_n0 + j * 16][b_kk ^ bsw] =                          \
                __uint_as_float(f2tf32(rbv[j]));                                 \
    }

    LOAD_CHUNK(0);
    STORE_CHUNK(0);
    __syncthreads();

    const int NT = KTOT / 16;
    for (int t = 0; t < NT; t++) {
        const int cur = t & 1;
        if (t + 1 < NT) LOAD_CHUNK((t + 1) * 16);

        #pragma unroll
        for (int kb8 = 0; kb8 < 2; kb8++) {
            uint32_t af[4][4], bf[4][2];
            #pragma unroll
            for (int mt = 0; mt < 4; mt++) {
                const int rlo = warpM + mt * 16 + g;
                const int rhi = rlo + 8;
                const int slo = (tig * 2) ^ rswz(rlo);
                const int shi = (tig * 2) ^ rswz(rhi);
                float2 lo = *(const float2*)&Asf[cur][kb8][rlo][slo];
                float2 hi = *(const float2*)&Asf[cur][kb8][rhi][shi];
                af[mt][0] = __float_as_uint(lo.x);   // (g,     tig)
                af[mt][1] = __float_as_uint(hi.x);   // (g+8,   tig)
                af[mt][2] = __float_as_uint(lo.y);   // (g,   tig+4)
                af[mt][3] = __float_as_uint(hi.y);   // (g+8, tig+4)
            }
            #pragma unroll
            for (int nt = 0; nt < 4; nt++) {
                const int n = warpN + nt * 8 + g;
                const int sn = (tig * 2) ^ rswz(n);
                float2 bb = *(const float2*)&Bsf[cur][kb8][n][sn];
                bf[nt][0] = __float_as_uint(bb.x);   // (k=tig,   n)
                bf[nt][1] = __float_as_uint(bb.y);   // (k=tig+4, n)
            }
            #pragma unroll
            for (int mt = 0; mt < 4; mt++)
                #pragma unroll
                for (int nt = 0; nt < 4; nt++)
                    mma_tf32_16x8x8(acc[mt][nt][0], acc[mt][nt][1],
                                    acc[mt][nt][2], acc[mt][nt][3],
                                    af[mt][0], af[mt][1], af[mt][2], af[mt][3],
                                    bf[nt][0], bf[nt][1]);
        }
        if (t + 1 < NT) STORE_CHUNK(cur ^ 1);
        __syncthreads();
    }
    #undef LOAD_CHUNK
    #undef STORE_CHUNK

    // ---- epilogue: BN(+bias)(+gate) and store ----
    const size_t bb = (size_t)b * C_ * HW_;
    #pragma unroll
    for (int mt = 0; mt < 4; mt++) {
        const int olo = o0 + warpM + mt * 16 + g;
        const int ohi = olo + 8;
        const float invlo = gma[olo] * rsqrtf(vr[olo] + EPS);
        const float addlo = bta[olo] - mnn[olo] * invlo + bias[olo] * invlo;
        const float invhi = gma[ohi] * rsqrtf(vr[ohi] + EPS);
        const float addhi = bta[ohi] - mnn[ohi] * invhi + bias[ohi] * invhi;
        #pragma unroll
        for (int nt = 0; nt < 4; nt++) {
            const int n = p0 + warpN + nt * 8 + 2 * tig;
            const size_t lo = bb + (size_t)olo * HW_ + n;
            const size_t hi = bb + (size_t)ohi * HW_ + n;
            float2 vlo, vhi;
            vlo.x = acc[mt][nt][0] * invlo + addlo;
            vlo.y = acc[mt][nt][1] * invlo + addlo;
            vhi.x = acc[mt][nt][2] * invhi + addhi;
            vhi.y = acc[mt][nt][3] * invhi + addhi;
            if (!IS_G1) {
                float2 xlo = *(const float2*)(xg + lo);
                float2 xhi = *(const float2*)(xg + hi);
                vlo.x *= xlo.x; vlo.y *= xlo.y;
                vhi.x *= xhi.x; vhi.y *= xhi.y;
            }
            *(float2*)(dst + lo) = vlo;
            *(float2*)(dst + hi) = vhi;
        }
    }
}

// ---------------- launch ----------------------------------------------------
extern "C" void kernel_launch(void* const* d_in, const int* in_sizes, int n_in,
                              void* d_out, int out_size) {
    const float* x          = (const float*)d_in[0];
    const float* edge_w     = (const float*)d_in[1];
    const float* edge_gamma = (const float*)d_in[2];
    const float* edge_beta  = (const float*)d_in[3];
    const float* edge_mean  = (const float*)d_in[4];
    const float* edge_var   = (const float*)d_in[5];
    const float* fc1_w      = (const float*)d_in[6];
    const float* fc2_w      = (const float*)d_in[7];
    const float* fusion_w   = (const float*)d_in[8];
    const float* fusion_b   = (const float*)d_in[9];
    const float* bn1_gamma  = (const float*)d_in[10];
    const float* bn1_beta   = (const float*)d_in[11];
    const float* bn1_mean   = (const float*)d_in[12];
    const float* bn1_var    = (const float*)d_in[13];
    const float* deform_w   = (const float*)d_in[14];
    const float* balance_w  = (const float*)d_in[15];
    const float* balance_b  = (const float*)d_in[16];
    const float* bn2_gamma  = (const float*)d_in[17];
    const float* bn2_beta   = (const float*)d_in[18];
    const float* bn2_mean   = (const float*)d_in[19];
    const float* bn2_var    = (const float*)d_in[20];
    float* out = (float*)d_out;

    float *pe = nullptr, *pt1 = nullptr, *pt2 = nullptr;
    cudaGetSymbolAddress((void**)&pe,  g_edge);
    cudaGetSymbolAddress((void**)&pt1, g_t1);
    cudaGetSymbolAddress((void**)&pt2, g_t2);

    const int nplanes = B_ * C_;

    // 1+3) edge branch dwconv + BN + ReLU -> g_edge, fused spatial mean -> g_avg
    dwconv_kernel<true, true><<<nplanes, 256>>>(x, edge_w, pe,
                                                edge_gamma, edge_beta,
                                                edge_mean, edge_var);
    // 2) SE MLP -> g_att
    se_kernel<<<1, 512>>>(fc1_w, fc2_w);
    // 4) fusion 1x1 conv (tf32 mma.sync, SE folded) + bias + BN1 -> g_t1
    dim3 grid(HW_ / 128, C_ / 128, B_);   // 32 x 2 x 32
    tgemm_kernel<512, true><<<grid, 256>>>(
        x, fusion_w, fusion_b, bn1_gamma, bn1_beta, bn1_mean, bn1_var, x, pt1);
    // 5) deform (zero-offset) dwconv -> g_t2
    dwconv_kernel<false, false><<<nplanes, 256>>>(pt1, deform_w, pt2,
                                                  nullptr, nullptr, nullptr, nullptr);
    // 6) balance 1x1 conv + bias + BN2, gated by x -> out
    tgemm_kernel<256, false><<<grid, 256>>>(
        pt2, balance_w, balance_b, bn2_gamma, bn2_beta, bn2_mean, bn2_var, x, out);
}

// round 9
// speedup vs baseline: 1.2721x; 1.2721x over previous
#include <cuda_runtime.h>
#include <cstdint>

#define B_  32
#define C_  256
#define H_  64
#define W_  64
#define HW_ 4096
#define EPS 1e-5f

// ---------------- scratch (device globals: no allocations allowed) ----------
__device__ float g_edge[(size_t)B_ * C_ * HW_];   // relu(bn(dwconv(x)))
__device__ float g_t1 [(size_t)B_ * C_ * HW_];    // bn1(fusion conv)
__device__ float g_t2 [(size_t)B_ * C_ * HW_];    // deform dwconv output
__device__ float g_avg[B_ * C_];
__device__ float g_att[B_ * C_];

// ---------------- 2) SE MLP -------------------------------------------------
__global__ __launch_bounds__(512) void se_kernel(const float* __restrict__ fc1_w,
                                                 const float* __restrict__ fc2_w) {
    __shared__ float sa[B_ * C_];
    __shared__ float shh[B_ * 16];
    int tid = threadIdx.x;
    for (int i = tid; i < B_ * C_; i += 512) sa[i] = g_avg[i];
    __syncthreads();
    {
        int b = tid >> 4, j = tid & 15;
        float s = 0.f;
        #pragma unroll 8
        for (int c = 0; c < C_; c++) s += sa[b * C_ + c] * fc1_w[j * C_ + c];
        shh[b * 16 + j] = fmaxf(s, 0.f);
    }
    __syncthreads();
    for (int idx = tid; idx < B_ * C_; idx += 512) {
        int b = idx >> 8, o = idx & 255;
        float s = 0.f;
        #pragma unroll
        for (int j = 0; j < 16; j++) s += shh[b * 16 + j] * fc2_w[o * 16 + j];
        g_att[idx] = 1.0f / (1.0f + expf(-s));
    }
}

// ------- 3/5) depthwise 3x3, register rotation; optional BN+ReLU / mean -----
template<bool BNRELU, bool DOMEAN>
__global__ __launch_bounds__(256) void dwconv_kernel(const float* __restrict__ src,
                                                     const float* __restrict__ w9,
                                                     float* __restrict__ dst,
                                                     const float* __restrict__ gma,
                                                     const float* __restrict__ bta,
                                                     const float* __restrict__ mn,
                                                     const float* __restrict__ vr) {
    __shared__ float sh[66][67];
    __shared__ float ws[8];
    int plane = blockIdx.x;
    int c = plane & (C_ - 1);
    const float* sp = src + (size_t)plane * HW_;
    int tid = threadIdx.x;
    for (int idx = tid; idx < 66 * 66; idx += 256) {
        int r = idx / 66, cc = idx - r * 66;
        int yy = r - 1, xx = cc - 1;
        float v = 0.f;
        if (yy >= 0 && yy < H_ && xx >= 0 && xx < W_) v = sp[yy * W_ + xx];
        sh[r][cc] = v;
    }
    float w[9];
    #pragma unroll
    for (int i = 0; i < 9; i++) w[i] = w9[c * 9 + i];
    float inv = 1.f, add = 0.f;
    if (BNRELU) { inv = gma[c] * rsqrtf(vr[c] + EPS); add = bta[c] - mn[c] * inv; }
    __syncthreads();

    const int col = tid & 63;
    const int r0  = (tid >> 6) << 4;
    float* dp = dst + (size_t)plane * HW_;

    float t0 = sh[r0][col],     t1 = sh[r0][col + 1],     t2 = sh[r0][col + 2];
    float m0 = sh[r0 + 1][col], m1 = sh[r0 + 1][col + 1], m2 = sh[r0 + 1][col + 2];
    float msum = 0.f;
    #pragma unroll
    for (int i = 0; i < 16; i++) {
        float b0 = sh[r0 + 2 + i][col];
        float b1 = sh[r0 + 2 + i][col + 1];
        float b2 = sh[r0 + 2 + i][col + 2];
        float s = w[0] * t0 + w[1] * t1 + w[2] * t2
                + w[3] * m0 + w[4] * m1 + w[5] * m2
                + w[6] * b0 + w[7] * b1 + w[8] * b2;
        if (DOMEAN) msum += m1;
        if (BNRELU) s = fmaxf(s * inv + add, 0.f);
        dp[(r0 + i) * W_ + col] = s;
        t0 = m0; t1 = m1; t2 = m2;
        m0 = b0; m1 = b1; m2 = b2;
    }

    if (DOMEAN) {
        #pragma unroll
        for (int o = 16; o; o >>= 1) msum += __shfl_xor_sync(0xffffffffu, msum, o);
        if ((tid & 31) == 0) ws[tid >> 5] = msum;
        __syncthreads();
        if (tid == 0) {
            float t = 0.f;
            #pragma unroll
            for (int i = 0; i < 8; i++) t += ws[i];
            g_avg[plane] = t * (1.0f / HW_);
        }
    }
}

// =================== tf32 mma.sync GEMM, 4-stage cp.async ===================
__device__ __forceinline__ uint32_t f2tf32(float x) {
    uint32_t r;
    asm("cvt.rna.tf32.f32 %0, %1;" : "=r"(r) : "f"(x));
    return r;
}
__device__ __forceinline__ uint32_t smem_u32(const void* p) {
    uint32_t a;
    asm("{ .reg .u64 t; cvta.to.shared.u64 t, %1; cvt.u32.u64 %0, t; }"
        : "=r"(a) : "l"(p));
    return a;
}
__device__ __forceinline__ void mma_tf32_16x8x8(
    float& d0, float& d1, float& d2, float& d3,
    uint32_t a0, uint32_t a1, uint32_t a2, uint32_t a3,
    uint32_t b0, uint32_t b1) {
    asm volatile(
        "mma.sync.aligned.m16n8k8.row.col.f32.tf32.tf32.f32 "
        "{%0,%1,%2,%3}, {%4,%5,%6,%7}, {%8,%9}, {%0,%1,%2,%3};"
        : "+f"(d0), "+f"(d1), "+f"(d2), "+f"(d3)
        : "r"(a0), "r"(a1), "r"(a2), "r"(a3), "r"(b0), "r"(b1));
}
#define CP16(dst, src) \
    asm volatile("cp.async.cg.shared.global [%0], [%1], 16;" :: "r"(dst), "l"(src))
#define CP_COMMIT() asm volatile("cp.async.commit_group;" ::: "memory")
#define CP_WAIT2()  asm volatile("cp.async.wait_group 2;" ::: "memory")

// Block tile: M=128 channels x N=128 pixels, K chunk 16, 8 warps (2M x 4N).
// A (weights) smem rows [m][20] floats; B (activations) rows [k][136] floats.
// tf32 conversion + SE att scaling happen at fragment load.
template<int KTOT, bool IS_G1>
__global__ __launch_bounds__(256, 2) void tgemm_kernel(
    const float* __restrict__ act,
    const float* __restrict__ wgt,
    const float* __restrict__ bias,
    const float* __restrict__ gma, const float* __restrict__ bta,
    const float* __restrict__ mnn, const float* __restrict__ vr,
    const float* __restrict__ xg,
    float* __restrict__ dst)
{
    extern __shared__ char smem[];
    constexpr int AROW = 20;                 // floats per A row (pad)
    constexpr int BROW = 136;                // floats per B row (pad)
    constexpr int ASTG = 128 * AROW * 4;     // 10240 B per stage
    constexpr int BSTG = 16 * BROW * 4;      // 8704 B per stage
    constexpr int AOFF = KTOT * 4;           // att_ext table first
    constexpr int BOFF = AOFF + 4 * ASTG;
    const uint32_t sb = smem_u32(smem);
    float* att_s = (float*)smem;

    const int tid = threadIdx.x;
    const int wid = tid >> 5, lane = tid & 31;
    const int g = lane >> 2, tig = lane & 3;
    const int b  = blockIdx.z;
    const int o0 = blockIdx.y * 128;
    const int p0 = blockIdx.x * 128;
    const int warpM = (wid & 1) * 64;
    const int warpN = (wid >> 1) * 32;

    const float* actb = act    + (size_t)b * C_ * HW_;
    const float* edgb = g_edge + (size_t)b * C_ * HW_;

    if (IS_G1) {
        const float* attb = g_att + b * C_;
        for (int i = tid; i < KTOT; i += 256)
            att_s[i] = (i < C_) ? attb[i] : 1.f;
    }

    // per-thread cp.async mappings (2 x 16B for A, 2 x 16B for B per chunk)
    const int am[2] = {  tid        >> 2, (tid + 256) >> 2 };
    const int aq[2] = {  tid         & 3, (tid + 256)  & 3 };
    const int bk[2] = {  tid        >> 5, (tid + 256) >> 5 };
    const int bc[2] = {  tid        & 31, (tid + 256) & 31 };

    #define ISSUE_CHUNK(T)                                                        \
    {                                                                             \
        const int slot_ = (T) & 3;                                                \
        const int k0_ = (T) * 16;                                                 \
        const uint32_t ab_ = sb + AOFF + slot_ * ASTG;                            \
        const uint32_t bb_ = sb + BOFF + slot_ * BSTG;                            \
        _Pragma("unroll")                                                         \
        for (int i = 0; i < 2; i++) {                                             \
            const float* as_ = wgt + (size_t)(o0 + am[i]) * KTOT + k0_ + aq[i]*4; \
            CP16(ab_ + (uint32_t)(am[i] * AROW + aq[i] * 4) * 4, as_);            \
            const int kg_ = k0_ + bk[i];                                          \
            const float* bs_;                                                     \
            if (IS_G1 && kg_ >= C_)                                               \
                bs_ = edgb + (size_t)(kg_ - C_) * HW_ + p0 + bc[i] * 4;           \
            else                                                                  \
                bs_ = actb + (size_t)kg_ * HW_ + p0 + bc[i] * 4;                  \
            CP16(bb_ + (uint32_t)(bk[i] * BROW + bc[i] * 4) * 4, bs_);            \
        }                                                                         \
    }

    float acc[4][4][4];
    #pragma unroll
    for (int i = 0; i < 4; i++)
        #pragma unroll
        for (int j = 0; j < 4; j++)
            #pragma unroll
            for (int q = 0; q < 4; q++) acc[i][j][q] = 0.f;

    const int NT = KTOT / 16;
    // prologue: 3 chunks in flight
    ISSUE_CHUNK(0); CP_COMMIT();
    ISSUE_CHUNK(1); CP_COMMIT();
    ISSUE_CHUNK(2); CP_COMMIT();

    for (int t = 0; t < NT; t++) {
        CP_WAIT2();
        __syncthreads();
        if (t + 3 < NT) ISSUE_CHUNK(t + 3);
        CP_COMMIT();

        const int slot = t & 3;
        const float* Ar = (const float*)(smem + AOFF + slot * ASTG);
        const float* Br = (const float*)(smem + BOFF + slot * BSTG);
        const int kb0 = t * 16;

        #pragma unroll
        for (int kb = 0; kb < 16; kb += 8) {
            float sa0 = 1.f, sa1 = 1.f;
            if (IS_G1) {
                sa0 = att_s[kb0 + kb + tig];
                sa1 = att_s[kb0 + kb + tig + 4];
            }
            uint32_t af[4][4], bf[4][2];
            #pragma unroll
            for (int mt = 0; mt < 4; mt++) {
                const int m = warpM + mt * 16 + g;
                af[mt][0] = f2tf32(Ar[m * AROW + kb + tig]);
                af[mt][1] = f2tf32(Ar[(m + 8) * AROW + kb + tig]);
                af[mt][2] = f2tf32(Ar[m * AROW + kb + tig + 4]);
                af[mt][3] = f2tf32(Ar[(m + 8) * AROW + kb + tig + 4]);
            }
            #pragma unroll
            for (int nt = 0; nt < 4; nt++) {
                const int n = warpN + nt * 8 + g;
                float b0 = Br[(kb + tig) * BROW + n];
                float b1 = Br[(kb + tig + 4) * BROW + n];
                if (IS_G1) { b0 *= sa0; b1 *= sa1; }
                bf[nt][0] = f2tf32(b0);
                bf[nt][1] = f2tf32(b1);
            }
            #pragma unroll
            for (int mt = 0; mt < 4; mt++)
                #pragma unroll
                for (int nt = 0; nt < 4; nt++)
                    mma_tf32_16x8x8(acc[mt][nt][0], acc[mt][nt][1],
                                    acc[mt][nt][2], acc[mt][nt][3],
                                    af[mt][0], af[mt][1], af[mt][2], af[mt][3],
                                    bf[nt][0], bf[nt][1]);
        }
        // no trailing sync: next iteration's wait+sync precedes slot reuse
    }
    #undef ISSUE_CHUNK

    // ---- epilogue: BN(+bias)(+gate) and store ----
    const size_t bb = (size_t)b * C_ * HW_;
    #pragma unroll
    for (int mt = 0; mt < 4; mt++) {
        const int olo = o0 + warpM + mt * 16 + g;
        const int ohi = olo + 8;
        const float invlo = gma[olo] * rsqrtf(vr[olo] + EPS);
        const float addlo = bta[olo] - mnn[olo] * invlo + bias[olo] * invlo;
        const float invhi = gma[ohi] * rsqrtf(vr[ohi] + EPS);
        const float addhi = bta[ohi] - mnn[ohi] * invhi + bias[ohi] * invhi;
        #pragma unroll
        for (int nt = 0; nt < 4; nt++) {
            const int n = p0 + warpN + nt * 8 + 2 * tig;
            const size_t lo = bb + (size_t)olo * HW_ + n;
            const size_t hi = bb + (size_t)ohi * HW_ + n;
            float2 vlo, vhi;
            vlo.x = acc[mt][nt][0] * invlo + addlo;
            vlo.y = acc[mt][nt][1] * invlo + addlo;
            vhi.x = acc[mt][nt][2] * invhi + addhi;
            vhi.y = acc[mt][nt][3] * invhi + addhi;
            if (!IS_G1) {
                float2 xlo = *(const float2*)(xg + lo);
                float2 xhi = *(const float2*)(xg + hi);
                vlo.x *= xlo.x; vlo.y *= xlo.y;
                vhi.x *= xhi.x; vhi.y *= xhi.y;
            }
            *(float2*)(dst + lo) = vlo;
            *(float2*)(dst + hi) = vhi;
        }
    }
}

// ---------------- launch ----------------------------------------------------
extern "C" void kernel_launch(void* const* d_in, const int* in_sizes, int n_in,
                              void* d_out, int out_size) {
    const float* x          = (const float*)d_in[0];
    const float* edge_w     = (const float*)d_in[1];
    const float* edge_gamma = (const float*)d_in[2];
    const float* edge_beta  = (const float*)d_in[3];
    const float* edge_mean  = (const float*)d_in[4];
    const float* edge_var   = (const float*)d_in[5];
    const float* fc1_w      = (const float*)d_in[6];
    const float* fc2_w      = (const float*)d_in[7];
    const float* fusion_w   = (const float*)d_in[8];
    const float* fusion_b   = (const float*)d_in[9];
    const float* bn1_gamma  = (const float*)d_in[10];
    const float* bn1_beta   = (const float*)d_in[11];
    const float* bn1_mean   = (const float*)d_in[12];
    const float* bn1_var    = (const float*)d_in[13];
    const float* deform_w   = (const float*)d_in[14];
    const float* balance_w  = (const float*)d_in[15];
    const float* balance_b  = (const float*)d_in[16];
    const float* bn2_gamma  = (const float*)d_in[17];
    const float* bn2_beta   = (const float*)d_in[18];
    const float* bn2_mean   = (const float*)d_in[19];
    const float* bn2_var    = (const float*)d_in[20];
    float* out = (float*)d_out;

    float *pe = nullptr, *pt1 = nullptr, *pt2 = nullptr;
    cudaGetSymbolAddress((void**)&pe,  g_edge);
    cudaGetSymbolAddress((void**)&pt1, g_t1);
    cudaGetSymbolAddress((void**)&pt2, g_t2);

    // dynamic smem: att(KTOT*4) + 4*(128*20*4) + 4*(16*136*4)
    const int SMEM_G1 = 512 * 4 + 4 * 10240 + 4 * 8704;   // 77824
    const int SMEM_G2 = 256 * 4 + 4 * 10240 + 4 * 8704;   // 76800
    cudaFuncSetAttribute(tgemm_kernel<512, true>,
                         cudaFuncAttributeMaxDynamicSharedMemorySize, SMEM_G1);
    cudaFuncSetAttribute(tgemm_kernel<256, false>,
                         cudaFuncAttributeMaxDynamicSharedMemorySize, SMEM_G2);

    const int nplanes = B_ * C_;

    // 1+3) edge dwconv + BN + ReLU -> g_edge, fused spatial mean -> g_avg
    dwconv_kernel<true, true><<<nplanes, 256>>>(x, edge_w, pe,
                                                edge_gamma, edge_beta,
                                                edge_mean, edge_var);
    // 2) SE MLP -> g_att
    se_kernel<<<1, 512>>>(fc1_w, fc2_w);
    // 4) fusion 1x1 conv (tf32 mma.sync + cp.async, SE folded) + BN1 -> g_t1
    dim3 grid(HW_ / 128, C_ / 128, B_);
    tgemm_kernel<512, true><<<grid, 256, SMEM_G1>>>(
        x, fusion_w, fusion_b, bn1_gamma, bn1_beta, bn1_mean, bn1_var, x, pt1);
    // 5) deform (zero-offset) dwconv -> g_t2
    dwconv_kernel<false, false><<<nplanes, 256>>>(pt1, deform_w, pt2,
                                                  nullptr, nullptr, nullptr, nullptr);
    // 6) balance 1x1 conv + bias + BN2, gated by x -> out
    tgemm_kernel<256, false><<<grid, 256, SMEM_G2>>>(
        pt2, balance_w, balance_b, bn2_gamma, bn2_beta, bn2_mean, bn2_var, x, out);
}

// round 10
// speedup vs baseline: 1.3724x; 1.0788x over previous
#include <cuda_runtime.h>
#include <cstdint>

#define B_  32
#define C_  256
#define H_  64
#define W_  64
#define HW_ 4096
#define EPS 1e-5f

// ---------------- scratch (device globals: no allocations allowed) ----------
__device__ float g_edge[(size_t)B_ * C_ * HW_];   // relu(bn(dwconv(x)))
__device__ float g_t1 [(size_t)B_ * C_ * HW_];    // bn1(fusion conv)
__device__ float g_t2 [(size_t)B_ * C_ * HW_];    // deform dwconv out (tf32-rounded)
__device__ float g_avg[B_ * C_];
__device__ float g_att[B_ * C_];
__device__ float g_wt1[C_ * 2 * C_];              // tf32-rounded fusion_w
__device__ float g_wt2[C_ * C_];                  // tf32-rounded balance_w

__device__ __forceinline__ uint32_t f2tf32(float x) {
    uint32_t r;
    asm("cvt.rna.tf32.f32 %0, %1;" : "=r"(r) : "f"(x));
    return r;
}

// ---------------- 0) weight pre-round to tf32 -------------------------------
__global__ __launch_bounds__(256) void wcvt_kernel(const float* __restrict__ w1,
                                                   const float* __restrict__ w2) {
    int i = blockIdx.x * 256 + threadIdx.x;
    if (i < C_ * 2 * C_) g_wt1[i] = __uint_as_float(f2tf32(w1[i]));
    if (i < C_ * C_)     g_wt2[i] = __uint_as_float(f2tf32(w2[i]));
}

// ---------------- 2) SE MLP -------------------------------------------------
__global__ __launch_bounds__(512) void se_kernel(const float* __restrict__ fc1_w,
                                                 const float* __restrict__ fc2_w) {
    __shared__ float sa[B_ * C_];
    __shared__ float shh[B_ * 16];
    int tid = threadIdx.x;
    for (int i = tid; i < B_ * C_; i += 512) sa[i] = g_avg[i];
    __syncthreads();
    {
        int b = tid >> 4, j = tid & 15;
        float s = 0.f;
        #pragma unroll 8
        for (int c = 0; c < C_; c++) s += sa[b * C_ + c] * fc1_w[j * C_ + c];
        shh[b * 16 + j] = fmaxf(s, 0.f);
    }
    __syncthreads();
    for (int idx = tid; idx < B_ * C_; idx += 512) {
        int b = idx >> 8, o = idx & 255;
        float s = 0.f;
        #pragma unroll
        for (int j = 0; j < 16; j++) s += shh[b * 16 + j] * fc2_w[o * 16 + j];
        g_att[idx] = 1.0f / (1.0f + expf(-s));
    }
}

// ------- 3/5) depthwise 3x3, 2 cols x 8 rows per thread, float2 path --------
template<bool BNRELU, bool DOMEAN, bool ROUND>
__global__ __launch_bounds__(256) void dwconv_kernel(const float* __restrict__ src,
                                                     const float* __restrict__ w9,
                                                     float* __restrict__ dst,
                                                     const float* __restrict__ gma,
                                                     const float* __restrict__ bta,
                                                     const float* __restrict__ mn,
                                                     const float* __restrict__ vr) {
    __shared__ float sh[66][68];
    __shared__ float ws[8];
    int plane = blockIdx.x;
    int c = plane & (C_ - 1);
    const float* sp = src + (size_t)plane * HW_;
    int tid = threadIdx.x;
    // phys col p holds image col p-1; p in [0,65]
    for (int idx = tid; idx < 66 * 66; idx += 256) {
        int r = idx / 66, cc = idx - r * 66;
        int yy = r - 1, xx = cc - 1;
        float v = 0.f;
        if (yy >= 0 && yy < H_ && xx >= 0 && xx < W_) v = sp[yy * W_ + xx];
        sh[r][cc] = v;
    }
    float w[9];
    #pragma unroll
    for (int i = 0; i < 9; i++) w[i] = w9[c * 9 + i];
    float inv = 1.f, add = 0.f;
    if (BNRELU) { inv = gma[c] * rsqrtf(vr[c] + EPS); add = bta[c] - mn[c] * inv; }
    __syncthreads();

    const int c0 = (tid & 31) * 2;            // output cols c0, c0+1
    const int r0 = (tid >> 5) * 8;            // 8-row strip
    float* dp = dst + (size_t)plane * HW_;

    // rotation buffers: 4 phys cols c0..c0+3 per row
    float2 ta = *(const float2*)&sh[r0][c0],     tb = *(const float2*)&sh[r0][c0 + 2];
    float2 ma = *(const float2*)&sh[r0 + 1][c0], mb = *(const float2*)&sh[r0 + 1][c0 + 2];
    float msum = 0.f;
    #pragma unroll
    for (int i = 0; i < 8; i++) {
        float2 ba = *(const float2*)&sh[r0 + 2 + i][c0];
        float2 bb = *(const float2*)&sh[r0 + 2 + i][c0 + 2];
        float s0 = w[0] * ta.x + w[1] * ta.y + w[2] * tb.x
                 + w[3] * ma.x + w[4] * ma.y + w[5] * mb.x
                 + w[6] * ba.x + w[7] * ba.y + w[8] * bb.x;
        float s1 = w[0] * ta.y + w[1] * tb.x + w[2] * tb.y
                 + w[3] * ma.y + w[4] * mb.x + w[5] * mb.y
                 + w[6] * ba.y + w[7] * bb.x + w[8] * bb.y;
        if (DOMEAN) msum += ma.y + mb.x;      // x[r0+i][c0], x[r0+i][c0+1]
        if (BNRELU) {
            s0 = fmaxf(s0 * inv + add, 0.f);
            s1 = fmaxf(s1 * inv + add, 0.f);
        }
        if (ROUND) {
            s0 = __uint_as_float(f2tf32(s0));
            s1 = __uint_as_float(f2tf32(s1));
        }
        *(float2*)&dp[(r0 + i) * W_ + c0] = make_float2(s0, s1);
        ta = ma; tb = mb;
        ma = ba; mb = bb;
    }

    if (DOMEAN) {
        #pragma unroll
        for (int o = 16; o; o >>= 1) msum += __shfl_xor_sync(0xffffffffu, msum, o);
        if ((tid & 31) == 0) ws[tid >> 5] = msum;
        __syncthreads();
        if (tid == 0) {
            float t = 0.f;
            #pragma unroll
            for (int i = 0; i < 8; i++) t += ws[i];
            g_avg[plane] = t * (1.0f / HW_);
        }
    }
}

// =================== tf32 mma.sync GEMM, 4-stage cp.async + ldmatrix ========
__device__ __forceinline__ uint32_t smem_u32(const void* p) {
    uint32_t a;
    asm("{ .reg .u64 t; cvta.to.shared.u64 t, %1; cvt.u32.u64 %0, t; }"
        : "=r"(a) : "l"(p));
    return a;
}
__device__ __forceinline__ void mma_tf32_16x8x8(
    float& d0, float& d1, float& d2, float& d3,
    uint32_t a0, uint32_t a1, uint32_t a2, uint32_t a3,
    uint32_t b0, uint32_t b1) {
    asm volatile(
        "mma.sync.aligned.m16n8k8.row.col.f32.tf32.tf32.f32 "
        "{%0,%1,%2,%3}, {%4,%5,%6,%7}, {%8,%9}, {%0,%1,%2,%3};"
        : "+f"(d0), "+f"(d1), "+f"(d2), "+f"(d3)
        : "r"(a0), "r"(a1), "r"(a2), "r"(a3), "r"(b0), "r"(b1));
}
__device__ __forceinline__ void ldsm_x4(uint32_t& r0, uint32_t& r1,
                                        uint32_t& r2, uint32_t& r3, uint32_t a) {
    asm volatile("ldmatrix.sync.aligned.m8n8.x4.shared.b16 {%0,%1,%2,%3}, [%4];"
                 : "=r"(r0), "=r"(r1), "=r"(r2), "=r"(r3) : "r"(a));
}
#define CP16(dst, src) \
    asm volatile("cp.async.cg.shared.global [%0], [%1], 16;" :: "r"(dst), "l"(src))
#define CP_COMMIT() asm volatile("cp.async.commit_group;" ::: "memory")
#define CP_WAIT2()  asm volatile("cp.async.wait_group 2;" ::: "memory")

// Block tile: M=128 channels x N=128 pixels, K chunk 16, 8 warps (2M x 4N).
// A = tf32-pre-rounded weights (ldmatrix fragments, no cvt).
// B = activations; CVT_B: cvt.rna + SE att scale at fragment load (gemm1 only;
// gemm2's B is tf32-pre-rounded by dwconv).
template<int KTOT, bool IS_G1>
__global__ __launch_bounds__(256, 2) void tgemm_kernel(
    const float* __restrict__ act,
    const float* __restrict__ wgt,    // pre-rounded tf32 weights
    const float* __restrict__ bias,
    const float* __restrict__ gma, const float* __restrict__ bta,
    const float* __restrict__ mnn, const float* __restrict__ vr,
    const float* __restrict__ xg,
    float* __restrict__ dst)
{
    extern __shared__ char smem[];
    constexpr int AROW = 20;                 // floats per A row (pad)
    constexpr int BROW = 136;                // floats per B row (pad)
    constexpr int ASTG = 128 * AROW * 4;     // 10240 B per stage
    constexpr int BSTG = 16 * BROW * 4;      // 8704 B per stage
    constexpr int AOFF = KTOT * 4;           // att_ext table first
    constexpr int BOFF = AOFF + 4 * ASTG;
    const uint32_t sb = smem_u32(smem);
    float* att_s = (float*)smem;

    const int tid = threadIdx.x;
    const int wid = tid >> 5, lane = tid & 31;
    const int g = lane >> 2, tig = lane & 3;
    const int b  = blockIdx.z;
    const int o0 = blockIdx.y * 128;
    const int p0 = blockIdx.x * 128;
    const int warpM = (wid & 1) * 64;
    const int warpN = (wid >> 1) * 32;

    const float* actb = act    + (size_t)b * C_ * HW_;
    const float* edgb = g_edge + (size_t)b * C_ * HW_;

    if (IS_G1) {
        const float* attb = g_att + b * C_;
        for (int i = tid; i < KTOT; i += 256)
            att_s[i] = (i < C_) ? attb[i] : 1.f;
    }

    // ldmatrix per-lane row offset (floats) within an A stage
    const int lrow = (lane & 7) + ((lane >> 3) & 1) * 8;
    const int lk   = (lane >> 4) * 4;
    const uint32_t a_lane_off = (uint32_t)((warpM + lrow) * AROW + lk) * 4;

    // per-thread cp.async mappings (2 x 16B for A, 2 x 16B for B per chunk)
    const int am[2] = {  tid        >> 2, (tid + 256) >> 2 };
    const int aq[2] = {  tid         & 3, (tid + 256)  & 3 };
    const int bk[2] = {  tid        >> 5, (tid + 256) >> 5 };
    const int bc[2] = {  tid        & 31, (tid + 256) & 31 };

    #define ISSUE_CHUNK(T)                                                        \
    {                                                                             \
        const int slot_ = (T) & 3;                                                \
        const int k0_ = (T) * 16;                                                 \
        const uint32_t ab_ = sb + AOFF + slot_ * ASTG;                            \
        const uint32_t bb_ = sb + BOFF + slot_ * BSTG;                            \
        _Pragma("unroll")                                                         \
        for (int i = 0; i < 2; i++) {                                             \
            const float* as_ = wgt + (size_t)(o0 + am[i]) * KTOT + k0_ + aq[i]*4; \
            CP16(ab_ + (uint32_t)(am[i] * AROW + aq[i] * 4) * 4, as_);            \
            const int kg_ = k0_ + bk[i];                                          \
            const float* bs_;                                                     \
            if (IS_G1 && kg_ >= C_)                                               \
                bs_ = edgb + (size_t)(kg_ - C_) * HW_ + p0 + bc[i] * 4;           \
            else                                                                  \
                bs_ = actb + (size_t)kg_ * HW_ + p0 + bc[i] * 4;                  \
            CP16(bb_ + (uint32_t)(bk[i] * BROW + bc[i] * 4) * 4, bs_);            \
        }                                                                         \
    }

    float acc[4][4][4];
    #pragma unroll
    for (int i = 0; i < 4; i++)
        #pragma unroll
        for (int j = 0; j < 4; j++)
            #pragma unroll
            for (int q = 0; q < 4; q++) acc[i][j][q] = 0.f;

    const int NT = KTOT / 16;
    ISSUE_CHUNK(0); CP_COMMIT();
    ISSUE_CHUNK(1); CP_COMMIT();
    ISSUE_CHUNK(2); CP_COMMIT();

    for (int t = 0; t < NT; t++) {
        CP_WAIT2();
        __syncthreads();
        if (t + 3 < NT) ISSUE_CHUNK(t + 3);
        CP_COMMIT();

        const int slot = t & 3;
        const uint32_t Aad = sb + AOFF + slot * ASTG + a_lane_off;
        const float* Br = (const float*)(smem + BOFF + slot * BSTG);
        const int kb0 = t * 16;

        #pragma unroll
        for (int kb = 0; kb < 16; kb += 8) {
            uint32_t af[4][4], bf[4][2];
            #pragma unroll
            for (int mt = 0; mt < 4; mt++)
                ldsm_x4(af[mt][0], af[mt][1], af[mt][2], af[mt][3],
                        Aad + (uint32_t)(mt * 16 * AROW + kb) * 4);
            if (IS_G1) {
                const float sa0 = att_s[kb0 + kb + tig];
                const float sa1 = att_s[kb0 + kb + tig + 4];
                #pragma unroll
                for (int nt = 0; nt < 4; nt++) {
                    const int n = warpN + nt * 8 + g;
                    bf[nt][0] = f2tf32(Br[(kb + tig) * BROW + n] * sa0);
                    bf[nt][1] = f2tf32(Br[(kb + tig + 4) * BROW + n] * sa1);
                }
            } else {
                #pragma unroll
                for (int nt = 0; nt < 4; nt++) {
                    const int n = warpN + nt * 8 + g;
                    bf[nt][0] = __float_as_uint(Br[(kb + tig) * BROW + n]);
                    bf[nt][1] = __float_as_uint(Br[(kb + tig + 4) * BROW + n]);
                }
            }
            #pragma unroll
            for (int mt = 0; mt < 4; mt++)
                #pragma unroll
                for (int nt = 0; nt < 4; nt++)
                    mma_tf32_16x8x8(acc[mt][nt][0], acc[mt][nt][1],
                                    acc[mt][nt][2], acc[mt][nt][3],
                                    af[mt][0], af[mt][1], af[mt][2], af[mt][3],
                                    bf[nt][0], bf[nt][1]);
        }
    }
    #undef ISSUE_CHUNK

    // ---- epilogue: BN(+bias)(+gate) and store ----
    const size_t bb = (size_t)b * C_ * HW_;
    #pragma unroll
    for (int mt = 0; mt < 4; mt++) {
        const int olo = o0 + warpM + mt * 16 + g;
        const int ohi = olo + 8;
        const float invlo = gma[olo] * rsqrtf(vr[olo] + EPS);
        const float addlo = bta[olo] - mnn[olo] * invlo + bias[olo] * invlo;
        const float invhi = gma[ohi] * rsqrtf(vr[ohi] + EPS);
        const float addhi = bta[ohi] - mnn[ohi] * invhi + bias[ohi] * invhi;
        #pragma unroll
        for (int nt = 0; nt < 4; nt++) {
            const int n = p0 + warpN + nt * 8 + 2 * tig;
            const size_t lo = bb + (size_t)olo * HW_ + n;
            const size_t hi = bb + (size_t)ohi * HW_ + n;
            float2 vlo, vhi;
            vlo.x = acc[mt][nt][0] * invlo + addlo;
            vlo.y = acc[mt][nt][1] * invlo + addlo;
            vhi.x = acc[mt][nt][2] * invhi + addhi;
            vhi.y = acc[mt][nt][3] * invhi + addhi;
            if (!IS_G1) {
                float2 xlo = *(const float2*)(xg + lo);
                float2 xhi = *(const float2*)(xg + hi);
                vlo.x *= xlo.x; vlo.y *= xlo.y;
                vhi.x *= xhi.x; vhi.y *= xhi.y;
            }
            *(float2*)(dst + lo) = vlo;
            *(float2*)(dst + hi) = vhi;
        }
    }
}

// ---------------- launch ----------------------------------------------------
extern "C" void kernel_launch(void* const* d_in, const int* in_sizes, int n_in,
                              void* d_out, int out_size) {
    const float* x          = (const float*)d_in[0];
    const float* edge_w     = (const float*)d_in[1];
    const float* edge_gamma = (const float*)d_in[2];
    const float* edge_beta  = (const float*)d_in[3];
    const float* edge_mean  = (const float*)d_in[4];
    const float* edge_var   = (const float*)d_in[5];
    const float* fc1_w      = (const float*)d_in[6];
    const float* fc2_w      = (const float*)d_in[7];
    const float* fusion_w   = (const float*)d_in[8];
    const float* fusion_b   = (const float*)d_in[9];
    const float* bn1_gamma  = (const float*)d_in[10];
    const float* bn1_beta   = (const float*)d_in[11];
    const float* bn1_mean   = (const float*)d_in[12];
    const float* bn1_var    = (const float*)d_in[13];
    const float* deform_w   = (const float*)d_in[14];
    const float* balance_w  = (const float*)d_in[15];
    const float* balance_b  = (const float*)d_in[16];
    const float* bn2_gamma  = (const float*)d_in[17];
    const float* bn2_beta   = (const float*)d_in[18];
    const float* bn2_mean   = (const float*)d_in[19];
    const float* bn2_var    = (const float*)d_in[20];
    float* out = (float*)d_out;

    float *pe = nullptr, *pt1 = nullptr, *pt2 = nullptr, *pw1 = nullptr, *pw2 = nullptr;
    cudaGetSymbolAddress((void**)&pe,  g_edge);
    cudaGetSymbolAddress((void**)&pt1, g_t1);
    cudaGetSymbolAddress((void**)&pt2, g_t2);
    cudaGetSymbolAddress((void**)&pw1, g_wt1);
    cudaGetSymbolAddress((void**)&pw2, g_wt2);

    const int SMEM_G1 = 512 * 4 + 4 * 10240 + 4 * 8704;   // 77824
    const int SMEM_G2 = 256 * 4 + 4 * 10240 + 4 * 8704;   // 76800
    cudaFuncSetAttribute(tgemm_kernel<512, true>,
                         cudaFuncAttributeMaxDynamicSharedMemorySize, SMEM_G1);
    cudaFuncSetAttribute(tgemm_kernel<256, false>,
                         cudaFuncAttributeMaxDynamicSharedMemorySize, SMEM_G2);

    const int nplanes = B_ * C_;

    // 0) pre-round weights to tf32
    wcvt_kernel<<<(C_ * 2 * C_ + 255) / 256, 256>>>(fusion_w, balance_w);
    // 1+3) edge dwconv + BN + ReLU -> g_edge, fused spatial mean -> g_avg
    dwconv_kernel<true, true, false><<<nplanes, 256>>>(x, edge_w, pe,
                                                       edge_gamma, edge_beta,
                                                       edge_mean, edge_var);
    // 2) SE MLP -> g_att
    se_kernel<<<1, 512>>>(fc1_w, fc2_w);
    // 4) fusion 1x1 conv (tf32 mma.sync + cp.async + ldmatrix) + BN1 -> g_t1
    dim3 grid(HW_ / 128, C_ / 128, B_);
    tgemm_kernel<512, true><<<grid, 256, SMEM_G1>>>(
        x, pw1, fusion_b, bn1_gamma, bn1_beta, bn1_mean, bn1_var, x, pt1);
    // 5) deform (zero-offset) dwconv -> g_t2 (tf32-rounded for gemm2)
    dwconv_kernel<false, false, true><<<nplanes, 256>>>(pt1, deform_w, pt2,
                                                        nullptr, nullptr,
                                                        nullptr, nullptr);
    // 6) balance 1x1 conv + bias + BN2, gated by x -> out
    tgemm_kernel<256, false><<<grid, 256, SMEM_G2>>>(
        pt2, pw2, balance_b, bn2_gamma, bn2_beta, bn2_mean, bn2_var, x, out);
}

// round 11
// speedup vs baseline: 1.4268x; 1.0397x over previous
#include <cuda_runtime.h>
#include <cstdint>

#define B_  32
#define C_  256
#define H_  64
#define W_  64
#define HW_ 4096
#define EPS 1e-5f

// ---------------- scratch (device globals: no allocations allowed) ----------
__device__ float g_edge[(size_t)B_ * C_ * HW_];   // relu(bn(dwconv(x)))
__device__ float g_t1 [(size_t)B_ * C_ * HW_];    // bn1(fusion conv)
__device__ float g_t2 [(size_t)B_ * C_ * HW_];    // deform dwconv out (tf32-rounded)
__device__ float g_avg[B_ * C_];
__device__ float g_att[B_ * C_];
__device__ float g_wt1[C_ * 2 * C_];              // tf32-rounded fusion_w
__device__ float g_wt2[C_ * C_];                  // tf32-rounded balance_w

__device__ __forceinline__ uint32_t f2tf32(float x) {
    uint32_t r;
    asm("cvt.rna.tf32.f32 %0, %1;" : "=r"(r) : "f"(x));
    return r;
}

// ---------------- 0) weight pre-round to tf32 -------------------------------
__global__ __launch_bounds__(256) void wcvt_kernel(const float* __restrict__ w1,
                                                   const float* __restrict__ w2) {
    int i = blockIdx.x * 256 + threadIdx.x;
    if (i < C_ * 2 * C_) g_wt1[i] = __uint_as_float(f2tf32(w1[i]));
    if (i < C_ * C_)     g_wt2[i] = __uint_as_float(f2tf32(w2[i]));
}

// ---------------- 2) SE MLP -------------------------------------------------
__global__ __launch_bounds__(512) void se_kernel(const float* __restrict__ fc1_w,
                                                 const float* __restrict__ fc2_w) {
    __shared__ float sa[B_ * C_];
    __shared__ float shh[B_ * 16];
    int tid = threadIdx.x;
    for (int i = tid; i < B_ * C_; i += 512) sa[i] = g_avg[i];
    __syncthreads();
    {
        int b = tid >> 4, j = tid & 15;
        float s = 0.f;
        #pragma unroll 8
        for (int c = 0; c < C_; c++) s += sa[b * C_ + c] * fc1_w[j * C_ + c];
        shh[b * 16 + j] = fmaxf(s, 0.f);
    }
    __syncthreads();
    for (int idx = tid; idx < B_ * C_; idx += 512) {
        int b = idx >> 8, o = idx & 255;
        float s = 0.f;
        #pragma unroll
        for (int j = 0; j < 16; j++) s += shh[b * 16 + j] * fc2_w[o * 16 + j];
        g_att[idx] = 1.0f / (1.0f + expf(-s));
    }
}

// ------- 3/5) depthwise 3x3, 2 cols x 8 rows per thread, float2 path --------
template<bool BNRELU, bool DOMEAN, bool ROUND>
__global__ __launch_bounds__(256) void dwconv_kernel(const float* __restrict__ src,
                                                     const float* __restrict__ w9,
                                                     float* __restrict__ dst,
                                                     const float* __restrict__ gma,
                                                     const float* __restrict__ bta,
                                                     const float* __restrict__ mn,
                                                     const float* __restrict__ vr) {
    __shared__ float sh[66][68];
    __shared__ float ws[8];
    int plane = blockIdx.x;
    int c = plane & (C_ - 1);
    const float* sp = src + (size_t)plane * HW_;
    int tid = threadIdx.x;
    for (int idx = tid; idx < 66 * 66; idx += 256) {
        int r = idx / 66, cc = idx - r * 66;
        int yy = r - 1, xx = cc - 1;
        float v = 0.f;
        if (yy >= 0 && yy < H_ && xx >= 0 && xx < W_) v = sp[yy * W_ + xx];
        sh[r][cc] = v;
    }
    float w[9];
    #pragma unroll
    for (int i = 0; i < 9; i++) w[i] = w9[c * 9 + i];
    float inv = 1.f, add = 0.f;
    if (BNRELU) { inv = gma[c] * rsqrtf(vr[c] + EPS); add = bta[c] - mn[c] * inv; }
    __syncthreads();

    const int c0 = (tid & 31) * 2;
    const int r0 = (tid >> 5) * 8;
    float* dp = dst + (size_t)plane * HW_;

    float2 ta = *(const float2*)&sh[r0][c0],     tb = *(const float2*)&sh[r0][c0 + 2];
    float2 ma = *(const float2*)&sh[r0 + 1][c0], mb = *(const float2*)&sh[r0 + 1][c0 + 2];
    float msum = 0.f;
    #pragma unroll
    for (int i = 0; i < 8; i++) {
        float2 ba = *(const float2*)&sh[r0 + 2 + i][c0];
        float2 bb = *(const float2*)&sh[r0 + 2 + i][c0 + 2];
        float s0 = w[0] * ta.x + w[1] * ta.y + w[2] * tb.x
                 + w[3] * ma.x + w[4] * ma.y + w[5] * mb.x
                 + w[6] * ba.x + w[7] * ba.y + w[8] * bb.x;
        float s1 = w[0] * ta.y + w[1] * tb.x + w[2] * tb.y
                 + w[3] * ma.y + w[4] * mb.x + w[5] * mb.y
                 + w[6] * ba.y + w[7] * bb.x + w[8] * bb.y;
        if (DOMEAN) msum += ma.y + mb.x;
        if (BNRELU) {
            s0 = fmaxf(s0 * inv + add, 0.f);
            s1 = fmaxf(s1 * inv + add, 0.f);
        }
        if (ROUND) {
            s0 = __uint_as_float(f2tf32(s0));
            s1 = __uint_as_float(f2tf32(s1));
        }
        *(float2*)&dp[(r0 + i) * W_ + c0] = make_float2(s0, s1);
        ta = ma; tb = mb;
        ma = ba; mb = bb;
    }

    if (DOMEAN) {
        #pragma unroll
        for (int o = 16; o; o >>= 1) msum += __shfl_xor_sync(0xffffffffu, msum, o);
        if ((tid & 31) == 0) ws[tid >> 5] = msum;
        __syncthreads();
        if (tid == 0) {
            float t = 0.f;
            #pragma unroll
            for (int i = 0; i < 8; i++) t += ws[i];
            g_avg[plane] = t * (1.0f / HW_);
        }
    }
}

// ========= tf32 mma.sync GEMM, K32 chunks, 3-stage cp.async + ldmatrix ======
__device__ __forceinline__ uint32_t smem_u32(const void* p) {
    uint32_t a;
    asm("{ .reg .u64 t; cvta.to.shared.u64 t, %1; cvt.u32.u64 %0, t; }"
        : "=r"(a) : "l"(p));
    return a;
}
__device__ __forceinline__ void mma_tf32_16x8x8(
    float& d0, float& d1, float& d2, float& d3,
    uint32_t a0, uint32_t a1, uint32_t a2, uint32_t a3,
    uint32_t b0, uint32_t b1) {
    asm volatile(
        "mma.sync.aligned.m16n8k8.row.col.f32.tf32.tf32.f32 "
        "{%0,%1,%2,%3}, {%4,%5,%6,%7}, {%8,%9}, {%0,%1,%2,%3};"
        : "+f"(d0), "+f"(d1), "+f"(d2), "+f"(d3)
        : "r"(a0), "r"(a1), "r"(a2), "r"(a3), "r"(b0), "r"(b1));
}
__device__ __forceinline__ void ldsm_x4(uint32_t& r0, uint32_t& r1,
                                        uint32_t& r2, uint32_t& r3, uint32_t a) {
    asm volatile("ldmatrix.sync.aligned.m8n8.x4.shared.b16 {%0,%1,%2,%3}, [%4];"
                 : "=r"(r0), "=r"(r1), "=r"(r2), "=r"(r3) : "r"(a));
}
#define CP16(dst, src) \
    asm volatile("cp.async.cg.shared.global [%0], [%1], 16;" :: "r"(dst), "l"(src))
#define CP_COMMIT() asm volatile("cp.async.commit_group;" ::: "memory")
#define CP_WAIT1()  asm volatile("cp.async.wait_group 1;" ::: "memory")

// Block tile: M=128 channels x N=128 pixels, K chunk 32, 8 warps (2M x 4N).
// A smem rows [m][36] floats; B smem rows [k][136] floats; 3 stages.
template<int KTOT, bool IS_G1>
__global__ __launch_bounds__(256, 2) void tgemm_kernel(
    const float* __restrict__ act,
    const float* __restrict__ wgt,    // pre-rounded tf32 weights
    const float* __restrict__ bias,
    const float* __restrict__ gma, const float* __restrict__ bta,
    const float* __restrict__ mnn, const float* __restrict__ vr,
    const float* __restrict__ xg,
    float* __restrict__ dst)
{
    extern __shared__ char smem[];
    constexpr int AROW = 36;                 // floats per A row (32 + pad)
    constexpr int BROW = 136;                // floats per B row (128 + pad)
    constexpr int ASTG = 128 * AROW * 4;     // 18432 B per stage
    constexpr int BSTG = 32 * BROW * 4;      // 17408 B per stage
    constexpr int AOFF = KTOT * 4;           // att_ext table first
    constexpr int BOFF = AOFF + 3 * ASTG;
    const uint32_t sb = smem_u32(smem);
    float* att_s = (float*)smem;

    const int tid = threadIdx.x;
    const int wid = tid >> 5, lane = tid & 31;
    const int g = lane >> 2, tig = lane & 3;
    const int b  = blockIdx.z;
    const int o0 = blockIdx.y * 128;
    const int p0 = blockIdx.x * 128;
    const int warpM = (wid & 1) * 64;
    const int warpN = (wid >> 1) * 32;

    const float* actb = act    + (size_t)b * C_ * HW_;
    const float* edgb = g_edge + (size_t)b * C_ * HW_;

    if (IS_G1) {
        const float* attb = g_att + b * C_;
        for (int i = tid; i < KTOT; i += 256)
            att_s[i] = (i < C_) ? attb[i] : 1.f;
    }

    // ldmatrix per-lane row offset within an A stage
    const int lrow = (lane & 7) + ((lane >> 3) & 1) * 8;
    const int lk   = (lane >> 4) * 4;
    const uint32_t a_lane_off = (uint32_t)((warpM + lrow) * AROW + lk) * 4;

    // cp.async mappings: 4 x 16B each for A and B per chunk
    // A: 128 rows x 8 quads = 1024 ops; B: 32 rows x 32 quads = 1024 ops
    #define ISSUE_CHUNK(T)                                                        \
    {                                                                             \
        const int slot_ = (T) % 3;                                                \
        const int k0_ = (T) * 32;                                                 \
        const uint32_t ab_ = sb + AOFF + slot_ * ASTG;                            \
        const uint32_t bb_ = sb + BOFF + slot_ * BSTG;                            \
        _Pragma("unroll")                                                         \
        for (int i = 0; i < 4; i++) {                                             \
            const int ai_ = tid + i * 256;                                        \
            const int am_ = ai_ >> 3, aq_ = ai_ & 7;                              \
            const float* as_ = wgt + (size_t)(o0 + am_) * KTOT + k0_ + aq_ * 4;   \
            CP16(ab_ + (uint32_t)(am_ * AROW + aq_ * 4) * 4, as_);                \
            const int bkr_ = ai_ >> 5, bcq_ = ai_ & 31;                           \
            const int kg_ = k0_ + bkr_;                                           \
            const float* bs_;                                                     \
            if (IS_G1 && kg_ >= C_)                                               \
                bs_ = edgb + (size_t)(kg_ - C_) * HW_ + p0 + bcq_ * 4;            \
            else                                                                  \
                bs_ = actb + (size_t)kg_ * HW_ + p0 + bcq_ * 4;                   \
            CP16(bb_ + (uint32_t)(bkr_ * BROW + bcq_ * 4) * 4, bs_);              \
        }                                                                         \
    }

    float acc[4][4][4];
    #pragma unroll
    for (int i = 0; i < 4; i++)
        #pragma unroll
        for (int j = 0; j < 4; j++)
            #pragma unroll
            for (int q = 0; q < 4; q++) acc[i][j][q] = 0.f;

    const int NT = KTOT / 32;
    ISSUE_CHUNK(0); CP_COMMIT();
    ISSUE_CHUNK(1); CP_COMMIT();

    for (int t = 0; t < NT; t++) {
        CP_WAIT1();
        __syncthreads();
        if (t + 2 < NT) ISSUE_CHUNK(t + 2);
        CP_COMMIT();

        const int slot = t % 3;
        const uint32_t Aad = sb + AOFF + slot * ASTG + a_lane_off;
        const float* Br = (const float*)(smem + BOFF + slot * BSTG);
        const int kb0 = t * 32;

        #pragma unroll
        for (int kb = 0; kb < 32; kb += 8) {
            uint32_t af[4][4], bf[4][2];
            #pragma unroll
            for (int mt = 0; mt < 4; mt++)
                ldsm_x4(af[mt][0], af[mt][1], af[mt][2], af[mt][3],
                        Aad + (uint32_t)(mt * 16 * AROW + kb) * 4);
            if (IS_G1) {
                const float sa0 = att_s[kb0 + kb + tig];
                const float sa1 = att_s[kb0 + kb + tig + 4];
                #pragma unroll
                for (int nt = 0; nt < 4; nt++) {
                    const int n = warpN + nt * 8 + g;
                    bf[nt][0] = f2tf32(Br[(kb + tig) * BROW + n] * sa0);
                    bf[nt][1] = f2tf32(Br[(kb + tig + 4) * BROW + n] * sa1);
                }
            } else {
                #pragma unroll
                for (int nt = 0; nt < 4; nt++) {
                    const int n = warpN + nt * 8 + g;
                    bf[nt][0] = __float_as_uint(Br[(kb + tig) * BROW + n]);
                    bf[nt][1] = __float_as_uint(Br[(kb + tig + 4) * BROW + n]);
                }
            }
            #pragma unroll
            for (int mt = 0; mt < 4; mt++)
                #pragma unroll
                for (int nt = 0; nt < 4; nt++)
                    mma_tf32_16x8x8(acc[mt][nt][0], acc[mt][nt][1],
                                    acc[mt][nt][2], acc[mt][nt][3],
                                    af[mt][0], af[mt][1], af[mt][2], af[mt][3],
                                    bf[nt][0], bf[nt][1]);
        }
    }
    #undef ISSUE_CHUNK

    // ---- epilogue: BN(+bias)(+gate) and store ----
    const size_t bb = (size_t)b * C_ * HW_;
    #pragma unroll
    for (int mt = 0; mt < 4; mt++) {
        const int olo = o0 + warpM + mt * 16 + g;
        const int ohi = olo + 8;
        const float invlo = gma[olo] * rsqrtf(vr[olo] + EPS);
        const float addlo = bta[olo] - mnn[olo] * invlo + bias[olo] * invlo;
        const float invhi = gma[ohi] * rsqrtf(vr[ohi] + EPS);
        const float addhi = bta[ohi] - mnn[ohi] * invhi + bias[ohi] * invhi;
        #pragma unroll
        for (int nt = 0; nt < 4; nt++) {
            const int n = p0 + warpN + nt * 8 + 2 * tig;
            const size_t lo = bb + (size_t)olo * HW_ + n;
            const size_t hi = bb + (size_t)ohi * HW_ + n;
            float2 vlo, vhi;
            vlo.x = acc[mt][nt][0] * invlo + addlo;
            vlo.y = acc[mt][nt][1] * invlo + addlo;
            vhi.x = acc[mt][nt][2] * invhi + addhi;
            vhi.y = acc[mt][nt][3] * invhi + addhi;
            if (!IS_G1) {
                float2 xlo = *(const float2*)(xg + lo);
                float2 xhi = *(const float2*)(xg + hi);
                vlo.x *= xlo.x; vlo.y *= xlo.y;
                vhi.x *= xhi.x; vhi.y *= xhi.y;
            }
            *(float2*)(dst + lo) = vlo;
            *(float2*)(dst + hi) = vhi;
        }
    }
}

// ---------------- launch ----------------------------------------------------
extern "C" void kernel_launch(void* const* d_in, const int* in_sizes, int n_in,
                              void* d_out, int out_size) {
    const float* x          = (const float*)d_in[0];
    const float* edge_w     = (const float*)d_in[1];
    const float* edge_gamma = (const float*)d_in[2];
    const float* edge_beta  = (const float*)d_in[3];
    const float* edge_mean  = (const float*)d_in[4];
    const float* edge_var   = (const float*)d_in[5];
    const float* fc1_w      = (const float*)d_in[6];
    const float* fc2_w      = (const float*)d_in[7];
    const float* fusion_w   = (const float*)d_in[8];
    const float* fusion_b   = (const float*)d_in[9];
    const float* bn1_gamma  = (const float*)d_in[10];
    const float* bn1_beta   = (const float*)d_in[11];
    const float* bn1_mean   = (const float*)d_in[12];
    const float* bn1_var    = (const float*)d_in[13];
    const float* deform_w   = (const float*)d_in[14];
    const float* balance_w  = (const float*)d_in[15];
    const float* balance_b  = (const float*)d_in[16];
    const float* bn2_gamma  = (const float*)d_in[17];
    const float* bn2_beta   = (const float*)d_in[18];
    const float* bn2_mean   = (const float*)d_in[19];
    const float* bn2_var    = (const float*)d_in[20];
    float* out = (float*)d_out;

    float *pe = nullptr, *pt1 = nullptr, *pt2 = nullptr, *pw1 = nullptr, *pw2 = nullptr;
    cudaGetSymbolAddress((void**)&pe,  g_edge);
    cudaGetSymbolAddress((void**)&pt1, g_t1);
    cudaGetSymbolAddress((void**)&pt2, g_t2);
    cudaGetSymbolAddress((void**)&pw1, g_wt1);
    cudaGetSymbolAddress((void**)&pw2, g_wt2);

    // smem: att(KTOT*4) + 3*ASTG(18432) + 3*BSTG(17408)
    const int SMEM_G1 = 512 * 4 + 3 * 18432 + 3 * 17408;  // 109568
    const int SMEM_G2 = 256 * 4 + 3 * 18432 + 3 * 17408;  // 108544
    cudaFuncSetAttribute(tgemm_kernel<512, true>,
                         cudaFuncAttributeMaxDynamicSharedMemorySize, SMEM_G1);
    cudaFuncSetAttribute(tgemm_kernel<256, false>,
                         cudaFuncAttributeMaxDynamicSharedMemorySize, SMEM_G2);

    const int nplanes = B_ * C_;

    // 0) pre-round weights to tf32
    wcvt_kernel<<<(C_ * 2 * C_ + 255) / 256, 256>>>(fusion_w, balance_w);
    // 1+3) edge dwconv + BN + ReLU -> g_edge, fused spatial mean -> g_avg
    dwconv_kernel<true, true, false><<<nplanes, 256>>>(x, edge_w, pe,
                                                       edge_gamma, edge_beta,
                                                       edge_mean, edge_var);
    // 2) SE MLP -> g_att
    se_kernel<<<1, 512>>>(fc1_w, fc2_w);
    // 4) fusion 1x1 conv (tf32 mma.sync, K32 chunks) + BN1 -> g_t1
    dim3 grid(HW_ / 128, C_ / 128, B_);
    tgemm_kernel<512, true><<<grid, 256, SMEM_G1>>>(
        x, pw1, fusion_b, bn1_gamma, bn1_beta, bn1_mean, bn1_var, x, pt1);
    // 5) deform (zero-offset) dwconv -> g_t2 (tf32-rounded for gemm2)
    dwconv_kernel<false, false, true><<<nplanes, 256>>>(pt1, deform_w, pt2,
                                                        nullptr, nullptr,
                                                        nullptr, nullptr);
    // 6) balance 1x1 conv + bias + BN2, gated by x -> out
    tgemm_kernel<256, false><<<grid, 256, SMEM_G2>>>(
        pt2, pw2, balance_b, bn2_gamma, bn2_beta, bn2_mean, bn2_var, x, out);
}

// round 13
// speedup vs baseline: 1.5068x; 1.0561x over previous
#include <cuda_runtime.h>
#include <cstdint>

#define B_  32
#define C_  256
#define H_  64
#define W_  64
#define HW_ 4096
#define EPS 1e-5f

// ---------------- scratch (device globals: no allocations allowed) ----------
__device__ float g_edge[(size_t)B_ * C_ * HW_];   // relu(bn(dwconv(x)))
__device__ float g_t1 [(size_t)B_ * C_ * HW_];    // bn1(fusion conv)
__device__ float g_t2 [(size_t)B_ * C_ * HW_];    // deform dwconv out (tf32-rounded)
__device__ float g_avg[B_ * C_];
__device__ float g_att[B_ * C_];
__device__ float g_wt1[C_ * 2 * C_];              // tf32-rounded fusion_w
__device__ float g_wt2[C_ * C_];                  // tf32-rounded balance_w

__device__ __forceinline__ uint32_t f2tf32(float x) {
    uint32_t r;
    asm("cvt.rna.tf32.f32 %0, %1;" : "=r"(r) : "f"(x));
    return r;
}

// ---------------- 0) weight pre-round to tf32 -------------------------------
__global__ __launch_bounds__(256) void wcvt_kernel(const float* __restrict__ w1,
                                                   const float* __restrict__ w2) {
    int i = blockIdx.x * 256 + threadIdx.x;
    if (i < C_ * 2 * C_) g_wt1[i] = __uint_as_float(f2tf32(w1[i]));
    if (i < C_ * C_)     g_wt2[i] = __uint_as_float(f2tf32(w2[i]));
}

// ---------------- 2) SE MLP -------------------------------------------------
__global__ __launch_bounds__(512) void se_kernel(const float* __restrict__ fc1_w,
                                                 const float* __restrict__ fc2_w) {
    __shared__ float sa[B_ * C_];
    __shared__ float shh[B_ * 16];
    int tid = threadIdx.x;
    for (int i = tid; i < B_ * C_; i += 512) sa[i] = g_avg[i];
    __syncthreads();
    {
        int b = tid >> 4, j = tid & 15;
        float s = 0.f;
        #pragma unroll 8
        for (int c = 0; c < C_; c++) s += sa[b * C_ + c] * fc1_w[j * C_ + c];
        shh[b * 16 + j] = fmaxf(s, 0.f);
    }
    __syncthreads();
    for (int idx = tid; idx < B_ * C_; idx += 512) {
        int b = idx >> 8, o = idx & 255;
        float s = 0.f;
        #pragma unroll
        for (int j = 0; j < 16; j++) s += shh[b * 16 + j] * fc2_w[o * 16 + j];
        g_att[idx] = 1.0f / (1.0f + expf(-s));
    }
}

// ------- 3/5) depthwise 3x3, vectorized fill, 2 cols x 8 rows per thread ----
template<bool BNRELU, bool DOMEAN, bool ROUND>
__global__ __launch_bounds__(256) void dwconv_kernel(const float* __restrict__ src,
                                                     const float* __restrict__ w9,
                                                     float* __restrict__ dst,
                                                     const float* __restrict__ gma,
                                                     const float* __restrict__ bta,
                                                     const float* __restrict__ mn,
                                                     const float* __restrict__ vr) {
    __shared__ float sh[66][68];      // phys col p = image col p-1; row r = image row r-1
    __shared__ float ws[8];
    int plane = blockIdx.x;
    int c = plane & (C_ - 1);
    const float* sp = src + (size_t)plane * HW_;
    int tid = threadIdx.x;

    // interior fill: image rows 0..63 -> phys rows 1..64, 16 float4 per row
    #pragma unroll
    for (int v = tid; v < 1024; v += 256) {
        int r = v >> 4, q = (v & 15) << 2;
        float4 val = *(const float4*)(sp + r * W_ + q);
        sh[r + 1][q + 1] = val.x;
        sh[r + 1][q + 2] = val.y;
        sh[r + 1][q + 3] = val.z;
        sh[r + 1][q + 4] = val.w;
    }
    // border zeros: rows 0 & 65 (cols 0..65); cols 0 & 65 (rows 1..64)
    if (tid < 132) {
        int cc = tid % 66, rr = (tid / 66) * 65;
        sh[rr][cc] = 0.f;
    } else if (tid < 196) {
        int i = tid - 132;            // 0..63 -> rows 1..64, both col borders
        sh[1 + i][0]  = 0.f;
        sh[1 + i][65] = 0.f;
    }

    float w[9];
    #pragma unroll
    for (int i = 0; i < 9; i++) w[i] = w9[c * 9 + i];
    float inv = 1.f, add = 0.f;
    if (BNRELU) { inv = gma[c] * rsqrtf(vr[c] + EPS); add = bta[c] - mn[c] * inv; }
    __syncthreads();

    const int c0 = (tid & 31) * 2;
    const int r0 = (tid >> 5) * 8;
    float* dp = dst + (size_t)plane * HW_;

    float2 ta = *(const float2*)&sh[r0][c0],     tb = *(const float2*)&sh[r0][c0 + 2];
    float2 ma = *(const float2*)&sh[r0 + 1][c0], mb = *(const float2*)&sh[r0 + 1][c0 + 2];
    float msum = 0.f;
    #pragma unroll
    for (int i = 0; i < 8; i++) {
        float2 ba = *(const float2*)&sh[r0 + 2 + i][c0];
        float2 bb = *(const float2*)&sh[r0 + 2 + i][c0 + 2];
        float s0 = w[0] * ta.x + w[1] * ta.y + w[2] * tb.x
                 + w[3] * ma.x + w[4] * ma.y + w[5] * mb.x
                 + w[6] * ba.x + w[7] * ba.y + w[8] * bb.x;
        float s1 = w[0] * ta.y + w[1] * tb.x + w[2] * tb.y
                 + w[3] * ma.y + w[4] * mb.x + w[5] * mb.y
                 + w[6] * ba.y + w[7] * bb.x + w[8] * bb.y;
        if (DOMEAN) msum += ma.y + mb.x;
        if (BNRELU) {
            s0 = fmaxf(s0 * inv + add, 0.f);
            s1 = fmaxf(s1 * inv + add, 0.f);
        }
        if (ROUND) {
            s0 = __uint_as_float(f2tf32(s0));
            s1 = __uint_as_float(f2tf32(s1));
        }
        *(float2*)&dp[(r0 + i) * W_ + c0] = make_float2(s0, s1);
        ta = ma; tb = mb;
        ma = ba; mb = bb;
    }

    if (DOMEAN) {
        #pragma unroll
        for (int o = 16; o; o >>= 1) msum += __shfl_xor_sync(0xffffffffu, msum, o);
        if ((tid & 31) == 0) ws[tid >> 5] = msum;
        __syncthreads();
        if (tid == 0) {
            float t = 0.f;
            #pragma unroll
            for (int i = 0; i < 8; i++) t += ws[i];
            g_avg[plane] = t * (1.0f / HW_);
        }
    }
}

// ===== tf32 mma.sync GEMM: K32 chunks, 4-stage cp.async, reg double-buffer ==
__device__ __forceinline__ uint32_t smem_u32(const void* p) {
    uint32_t a;
    asm("{ .reg .u64 t; cvta.to.shared.u64 t, %1; cvt.u32.u64 %0, t; }"
        : "=r"(a) : "l"(p));
    return a;
}
__device__ __forceinline__ void mma_tf32_16x8x8(
    float& d0, float& d1, float& d2, float& d3,
    uint32_t a0, uint32_t a1, uint32_t a2, uint32_t a3,
    uint32_t b0, uint32_t b1) {
    asm volatile(
        "mma.sync.aligned.m16n8k8.row.col.f32.tf32.tf32.f32 "
        "{%0,%1,%2,%3}, {%4,%5,%6,%7}, {%8,%9}, {%0,%1,%2,%3};"
        : "+f"(d0), "+f"(d1), "+f"(d2), "+f"(d3)
        : "r"(a0), "r"(a1), "r"(a2), "r"(a3), "r"(b0), "r"(b1));
}
__device__ __forceinline__ void ldsm_x4(uint32_t& r0, uint32_t& r1,
                                        uint32_t& r2, uint32_t& r3, uint32_t a) {
    asm volatile("ldmatrix.sync.aligned.m8n8.x4.shared.b16 {%0,%1,%2,%3}, [%4];"
                 : "=r"(r0), "=r"(r1), "=r"(r2), "=r"(r3) : "r"(a));
}
#define CP16(dst, src) \
    asm volatile("cp.async.cg.shared.global [%0], [%1], 16;" :: "r"(dst), "l"(src))
#define CP_COMMIT() asm volatile("cp.async.commit_group;" ::: "memory")
// all but the 2 most-recent groups must be complete -> chunk t has landed
#define CP_WAIT2()  asm volatile("cp.async.wait_group 2;" ::: "memory")

// Block tile: M=128 channels x N=128 pixels, K chunk 32, 8 warps (2M x 4N).
// A smem rows [m][36] floats; B smem rows [k][136] floats; 4 stages; 1 CTA/SM.
template<int KTOT, bool IS_G1>
__global__ __launch_bounds__(256) void tgemm_kernel(
    const float* __restrict__ act,
    const float* __restrict__ wgt,    // pre-rounded tf32 weights
    const float* __restrict__ bias,
    const float* __restrict__ gma, const float* __restrict__ bta,
    const float* __restrict__ mnn, const float* __restrict__ vr,
    const float* __restrict__ xg,
    float* __restrict__ dst)
{
    extern __shared__ char smem[];
    constexpr int AROW = 36;                 // floats per A row (32 + pad)
    constexpr int BROW = 136;                // floats per B row (128 + pad)
    constexpr int ASTG = 128 * AROW * 4;     // 18432 B per stage
    constexpr int BSTG = 32 * BROW * 4;      // 17408 B per stage
    constexpr int AOFF = KTOT * 4;           // att_ext table first
    constexpr int BOFF = AOFF + 4 * ASTG;
    const uint32_t sb = smem_u32(smem);
    float* att_s = (float*)smem;

    const int tid = threadIdx.x;
    const int wid = tid >> 5, lane = tid & 31;
    const int g = lane >> 2, tig = lane & 3;
    const int b  = blockIdx.z;
    const int o0 = blockIdx.y * 128;
    const int p0 = blockIdx.x * 128;
    const int warpM = (wid & 1) * 64;
    const int warpN = (wid >> 1) * 32;

    const float* actb = act    + (size_t)b * C_ * HW_;
    const float* edgb = g_edge + (size_t)b * C_ * HW_;

    if (IS_G1) {
        const float* attb = g_att + b * C_;
        for (int i = tid; i < KTOT; i += 256)
            att_s[i] = (i < C_) ? attb[i] : 1.f;
    }

    // ldmatrix per-lane row offset within an A stage
    const int lrow = (lane & 7) + ((lane >> 3) & 1) * 8;
    const int lk   = (lane >> 4) * 4;
    const uint32_t a_lane_off = (uint32_t)((warpM + lrow) * AROW + lk) * 4;

    #define ISSUE_CHUNK(T)                                                        \
    {                                                                             \
        const int slot_ = (T) & 3;                                                \
        const int k0_ = (T) * 32;                                                 \
        const uint32_t ab_ = sb + AOFF + slot_ * ASTG;                            \
        const uint32_t bb_ = sb + BOFF + slot_ * BSTG;                            \
        _Pragma("unroll")                                                         \
        for (int i = 0; i < 4; i++) {                                             \
            const int ai_ = tid + i * 256;                                        \
            const int am_ = ai_ >> 3, aq_ = ai_ & 7;                              \
            const float* as_ = wgt + (size_t)(o0 + am_) * KTOT + k0_ + aq_ * 4;   \
            CP16(ab_ + (uint32_t)(am_ * AROW + aq_ * 4) * 4, as_);                \
            const int bkr_ = ai_ >> 5, bcq_ = ai_ & 31;                           \
            const int kg_ = k0_ + bkr_;                                           \
            const float* bs_;                                                     \
            if (IS_G1 && kg_ >= C_)                                               \
                bs_ = edgb + (size_t)(kg_ - C_) * HW_ + p0 + bcq_ * 4;            \
            else                                                                  \
                bs_ = actb + (size_t)kg_ * HW_ + p0 + bcq_ * 4;                   \
            CP16(bb_ + (uint32_t)(bkr_ * BROW + bcq_ * 4) * 4, bs_);              \
        }                                                                         \
    }

    #define LOAD_AFRAG(D, KB)                                                     \
        _Pragma("unroll")                                                         \
        for (int mt = 0; mt < 4; mt++)                                            \
            ldsm_x4(af[D][mt][0], af[D][mt][1], af[D][mt][2], af[D][mt][3],       \
                    Aad + (uint32_t)(mt * 16 * AROW + (KB)) * 4);

    #define LOAD_BFRAG(D, KB)                                                     \
        if (IS_G1) {                                                              \
            const float sa0_ = att_s[kb0 + (KB) + tig];                           \
            const float sa1_ = att_s[kb0 + (KB) + tig + 4];                       \
            _Pragma("unroll")                                                     \
            for (int nt = 0; nt < 4; nt++) {                                      \
                const int n_ = warpN + nt * 8 + g;                                \
                bf[D][nt][0] = f2tf32(Br[((KB) + tig) * BROW + n_] * sa0_);       \
                bf[D][nt][1] = f2tf32(Br[((KB) + tig + 4) * BROW + n_] * sa1_);   \
            }                                                                     \
        } else {                                                                  \
            _Pragma("unroll")                                                     \
            for (int nt = 0; nt < 4; nt++) {                                      \
                const int n_ = warpN + nt * 8 + g;                                \
                bf[D][nt][0] = __float_as_uint(Br[((KB) + tig) * BROW + n_]);     \
                bf[D][nt][1] = __float_as_uint(Br[((KB) + tig + 4) * BROW + n_]); \
            }                                                                     \
        }

    #define MMA_BLOCK(D)                                                          \
        _Pragma("unroll")                                                         \
        for (int mt = 0; mt < 4; mt++)                                            \
            _Pragma("unroll")                                                     \
            for (int nt = 0; nt < 4; nt++)                                        \
                mma_tf32_16x8x8(acc[mt][nt][0], acc[mt][nt][1],                   \
                                acc[mt][nt][2], acc[mt][nt][3],                   \
                                af[D][mt][0], af[D][mt][1],                       \
                                af[D][mt][2], af[D][mt][3],                       \
                                bf[D][nt][0], bf[D][nt][1]);

    float acc[4][4][4];
    #pragma unroll
    for (int i = 0; i < 4; i++)
        #pragma unroll
        for (int j = 0; j < 4; j++)
            #pragma unroll
            for (int q = 0; q < 4; q++) acc[i][j][q] = 0.f;

    uint32_t af[2][4][4], bf[2][4][2];

    const int NT = KTOT / 32;
    ISSUE_CHUNK(0); CP_COMMIT();
    ISSUE_CHUNK(1); CP_COMMIT();
    ISSUE_CHUNK(2); CP_COMMIT();

    for (int t = 0; t < NT; t++) {
        CP_WAIT2();           // chunk t guaranteed landed
        __syncthreads();
        const int slot = t & 3;
        const uint32_t Aad = sb + AOFF + slot * ASTG + a_lane_off;
        const float* Br = (const float*)(smem + BOFF + slot * BSTG);
        const int kb0 = t * 32;

        // prefetch block 0 fragments immediately after the barrier
        LOAD_AFRAG(0, 0);
        LOAD_BFRAG(0, 0);

        if (t + 3 < NT) ISSUE_CHUNK(t + 3);
        CP_COMMIT();

        #pragma unroll
        for (int kb8 = 0; kb8 < 4; kb8++) {
            const int cur = kb8 & 1, nxt = cur ^ 1;
            if (kb8 < 3) {
                const int kbn = (kb8 + 1) * 8;
                LOAD_AFRAG(nxt, kbn);
                LOAD_BFRAG(nxt, kbn);
            }
            MMA_BLOCK(cur);
        }
    }
    #undef ISSUE_CHUNK
    #undef LOAD_AFRAG
    #undef LOAD_BFRAG
    #undef MMA_BLOCK

    // ---- epilogue: BN(+bias)(+gate) and store ----
    const size_t bb = (size_t)b * C_ * HW_;
    #pragma unroll
    for (int mt = 0; mt < 4; mt++) {
        const int olo = o0 + warpM + mt * 16 + g;
        const int ohi = olo + 8;
        const float invlo = gma[olo] * rsqrtf(vr[olo] + EPS);
        const float addlo = bta[olo] - mnn[olo] * invlo + bias[olo] * invlo;
        const float invhi = gma[ohi] * rsqrtf(vr[ohi] + EPS);
        const float addhi = bta[ohi] - mnn[ohi] * invhi + bias[ohi] * invhi;
        #pragma unroll
        for (int nt = 0; nt < 4; nt++) {
            const int n = p0 + warpN + nt * 8 + 2 * tig;
            const size_t lo = bb + (size_t)olo * HW_ + n;
            const size_t hi = bb + (size_t)ohi * HW_ + n;
            float2 vlo, vhi;
            vlo.x = acc[mt][nt][0] * invlo + addlo;
            vlo.y = acc[mt][nt][1] * invlo + addlo;
            vhi.x = acc[mt][nt][2] * invhi + addhi;
            vhi.y = acc[mt][nt][3] * invhi + addhi;
            if (!IS_G1) {
                float2 xlo = *(const float2*)(xg + lo);
                float2 xhi = *(const float2*)(xg + hi);
                vlo.x *= xlo.x; vlo.y *= xlo.y;
                vhi.x *= xhi.x; vhi.y *= xhi.y;
            }
            *(float2*)(dst + lo) = vlo;
            *(float2*)(dst + hi) = vhi;
        }
    }
}

// ---------------- launch ----------------------------------------------------
extern "C" void kernel_launch(void* const* d_in, const int* in_sizes, int n_in,
                              void* d_out, int out_size) {
    const float* x          = (const float*)d_in[0];
    const float* edge_w     = (const float*)d_in[1];
    const float* edge_gamma = (const float*)d_in[2];
    const float* edge_beta  = (const float*)d_in[3];
    const float* edge_mean  = (const float*)d_in[4];
    const float* edge_var   = (const float*)d_in[5];
    const float* fc1_w      = (const float*)d_in[6];
    const float* fc2_w      = (const float*)d_in[7];
    const float* fusion_w   = (const float*)d_in[8];
    const float* fusion_b   = (const float*)d_in[9];
    const float* bn1_gamma  = (const float*)d_in[10];
    const float* bn1_beta   = (const float*)d_in[11];
    const float* bn1_mean   = (const float*)d_in[12];
    const float* bn1_var    = (const float*)d_in[13];
    const float* deform_w   = (const float*)d_in[14];
    const float* balance_w  = (const float*)d_in[15];
    const float* balance_b  = (const float*)d_in[16];
    const float* bn2_gamma  = (const float*)d_in[17];
    const float* bn2_beta   = (const float*)d_in[18];
    const float* bn2_mean   = (const float*)d_in[19];
    const float* bn2_var    = (const float*)d_in[20];
    float* out = (float*)d_out;

    float *pe = nullptr, *pt1 = nullptr, *pt2 = nullptr, *pw1 = nullptr, *pw2 = nullptr;
    cudaGetSymbolAddress((void**)&pe,  g_edge);
    cudaGetSymbolAddress((void**)&pt1, g_t1);
    cudaGetSymbolAddress((void**)&pt2, g_t2);
    cudaGetSymbolAddress((void**)&pw1, g_wt1);
    cudaGetSymbolAddress((void**)&pw2, g_wt2);

    // smem: att(KTOT*4) + 4*ASTG(18432) + 4*BSTG(17408)
    const int SMEM_G1 = 512 * 4 + 4 * 18432 + 4 * 17408;  // 145408
    const int SMEM_G2 = 256 * 4 + 4 * 18432 + 4 * 17408;  // 144384
    cudaFuncSetAttribute(tgemm_kernel<512, true>,
                         cudaFuncAttributeMaxDynamicSharedMemorySize, SMEM_G1);
    cudaFuncSetAttribute(tgemm_kernel<256, false>,
                         cudaFuncAttributeMaxDynamicSharedMemorySize, SMEM_G2);

    const int nplanes = B_ * C_;

    // 0) pre-round weights to tf32
    wcvt_kernel<<<(C_ * 2 * C_ + 255) / 256, 256>>>(fusion_w, balance_w);
    // 1+3) edge dwconv + BN + ReLU -> g_edge, fused spatial mean -> g_avg
    dwconv_kernel<true, true, false><<<nplanes, 256>>>(x, edge_w, pe,
                                                       edge_gamma, edge_beta,
                                                       edge_mean, edge_var);
    // 2) SE MLP -> g_att
    se_kernel<<<1, 512>>>(fc1_w, fc2_w);
    // 4) fusion 1x1 conv (tf32 mma.sync, 4-stage, reg double-buffer) -> g_t1
    dim3 grid(HW_ / 128, C_ / 128, B_);
    tgemm_kernel<512, true><<<grid, 256, SMEM_G1>>>(
        x, pw1, fusion_b, bn1_gamma, bn1_beta, bn1_mean, bn1_var, x, pt1);
    // 5) deform (zero-offset) dwconv -> g_t2 (tf32-rounded for gemm2)
    dwconv_kernel<false, false, true><<<nplanes, 256>>>(pt1, deform_w, pt2,
                                                        nullptr, nullptr,
                                                        nullptr, nullptr);
    // 6) balance 1x1 conv + bias + BN2, gated by x -> out
    tgemm_kernel<256, false><<<grid, 256, SMEM_G2>>>(
        pt2, pw2, balance_b, bn2_gamma, bn2_beta, bn2_mean, bn2_var, x, out);
}

// round 14
// speedup vs baseline: 1.7239x; 1.1441x over previous
#include <cuda_runtime.h>
#include <cstdint>

#define B_  32
#define C_  256
#define H_  64
#define W_  64
#define HW_ 4096
#define EPS 1e-5f

// ---------------- scratch (device globals: no allocations allowed) ----------
__device__ float g_edge[(size_t)B_ * C_ * HW_];   // relu(bn(dwconv(x)))
__device__ float g_t1 [(size_t)B_ * C_ * HW_];    // bn1(fusion conv)
__device__ float g_t2 [(size_t)B_ * C_ * HW_];    // deform dwconv out (tf32-rounded)
__device__ float g_avg[B_ * C_];
__device__ float g_att[B_ * C_];
__device__ float g_wt1[C_ * 2 * C_];              // tf32-rounded fusion_w
__device__ float g_wt2[C_ * C_];                  // tf32-rounded balance_w

__device__ __forceinline__ uint32_t f2tf32(float x) {
    uint32_t r;
    asm("cvt.rna.tf32.f32 %0, %1;" : "=r"(r) : "f"(x));
    return r;
}

// ---------------- 0) weight pre-round to tf32 -------------------------------
__global__ __launch_bounds__(256) void wcvt_kernel(const float* __restrict__ w1,
                                                   const float* __restrict__ w2) {
    int i = blockIdx.x * 256 + threadIdx.x;
    if (i < C_ * 2 * C_) g_wt1[i] = __uint_as_float(f2tf32(w1[i]));
    if (i < C_ * C_)     g_wt2[i] = __uint_as_float(f2tf32(w2[i]));
}

// ---------------- 2) SE MLP -------------------------------------------------
__global__ __launch_bounds__(512) void se_kernel(const float* __restrict__ fc1_w,
                                                 const float* __restrict__ fc2_w) {
    __shared__ float sa[B_ * C_];
    __shared__ float shh[B_ * 16];
    int tid = threadIdx.x;
    for (int i = tid; i < B_ * C_; i += 512) sa[i] = g_avg[i];
    __syncthreads();
    {
        int b = tid >> 4, j = tid & 15;
        float s = 0.f;
        #pragma unroll 8
        for (int c = 0; c < C_; c++) s += sa[b * C_ + c] * fc1_w[j * C_ + c];
        shh[b * 16 + j] = fmaxf(s, 0.f);
    }
    __syncthreads();
    for (int idx = tid; idx < B_ * C_; idx += 512) {
        int b = idx >> 8, o = idx & 255;
        float s = 0.f;
        #pragma unroll
        for (int j = 0; j < 16; j++) s += shh[b * 16 + j] * fc2_w[o * 16 + j];
        g_att[idx] = 1.0f / (1.0f + expf(-s));
    }
}

// ------- 3/5) depthwise 3x3, vectorized fill, 2 cols x 8 rows per thread ----
template<bool BNRELU, bool DOMEAN, bool ROUND>
__global__ __launch_bounds__(256) void dwconv_kernel(const float* __restrict__ src,
                                                     const float* __restrict__ w9,
                                                     float* __restrict__ dst,
                                                     const float* __restrict__ gma,
                                                     const float* __restrict__ bta,
                                                     const float* __restrict__ mn,
                                                     const float* __restrict__ vr) {
    __shared__ float sh[66][68];      // phys col p = image col p-1; row r = image row r-1
    __shared__ float ws[8];
    int plane = blockIdx.x;
    int c = plane & (C_ - 1);
    const float* sp = src + (size_t)plane * HW_;
    int tid = threadIdx.x;

    // interior fill: image rows 0..63 -> phys rows 1..64, 16 float4 per row
    #pragma unroll
    for (int v = tid; v < 1024; v += 256) {
        int r = v >> 4, q = (v & 15) << 2;
        float4 val = *(const float4*)(sp + r * W_ + q);
        sh[r + 1][q + 1] = val.x;
        sh[r + 1][q + 2] = val.y;
        sh[r + 1][q + 3] = val.z;
        sh[r + 1][q + 4] = val.w;
    }
    // border zeros: rows 0 & 65 (cols 0..65); cols 0 & 65 (rows 1..64)
    if (tid < 132) {
        int cc = tid % 66, rr = (tid / 66) * 65;
        sh[rr][cc] = 0.f;
    } else if (tid < 196) {
        int i = tid - 132;            // 0..63 -> rows 1..64, both col borders
        sh[1 + i][0]  = 0.f;
        sh[1 + i][65] = 0.f;
    }

    float w[9];
    #pragma unroll
    for (int i = 0; i < 9; i++) w[i] = w9[c * 9 + i];
    float inv = 1.f, add = 0.f;
    if (BNRELU) { inv = gma[c] * rsqrtf(vr[c] + EPS); add = bta[c] - mn[c] * inv; }
    __syncthreads();

    const int c0 = (tid & 31) * 2;
    const int r0 = (tid >> 5) * 8;
    float* dp = dst + (size_t)plane * HW_;

    float2 ta = *(const float2*)&sh[r0][c0],     tb = *(const float2*)&sh[r0][c0 + 2];
    float2 ma = *(const float2*)&sh[r0 + 1][c0], mb = *(const float2*)&sh[r0 + 1][c0 + 2];
    float msum = 0.f;
    #pragma unroll
    for (int i = 0; i < 8; i++) {
        float2 ba = *(const float2*)&sh[r0 + 2 + i][c0];
        float2 bb = *(const float2*)&sh[r0 + 2 + i][c0 + 2];
        float s0 = w[0] * ta.x + w[1] * ta.y + w[2] * tb.x
                 + w[3] * ma.x + w[4] * ma.y + w[5] * mb.x
                 + w[6] * ba.x + w[7] * ba.y + w[8] * bb.x;
        float s1 = w[0] * ta.y + w[1] * tb.x + w[2] * tb.y
                 + w[3] * ma.y + w[4] * mb.x + w[5] * mb.y
                 + w[6] * ba.y + w[7] * bb.x + w[8] * bb.y;
        if (DOMEAN) msum += ma.y + mb.x;
        if (BNRELU) {
            s0 = fmaxf(s0 * inv + add, 0.f);
            s1 = fmaxf(s1 * inv + add, 0.f);
        }
        if (ROUND) {
            s0 = __uint_as_float(f2tf32(s0));
            s1 = __uint_as_float(f2tf32(s1));
        }
        *(float2*)&dp[(r0 + i) * W_ + c0] = make_float2(s0, s1);
        ta = ma; tb = mb;
        ma = ba; mb = bb;
    }

    if (DOMEAN) {
        #pragma unroll
        for (int o = 16; o; o >>= 1) msum += __shfl_xor_sync(0xffffffffu, msum, o);
        if ((tid & 31) == 0) ws[tid >> 5] = msum;
        __syncthreads();
        if (tid == 0) {
            float t = 0.f;
            #pragma unroll
            for (int i = 0; i < 8; i++) t += ws[i];
            g_avg[plane] = t * (1.0f / HW_);
        }
    }
}

// ========= tf32 mma.sync GEMM, K32 chunks, 3-stage cp.async + ldmatrix ======
__device__ __forceinline__ uint32_t smem_u32(const void* p) {
    uint32_t a;
    asm("{ .reg .u64 t; cvta.to.shared.u64 t, %1; cvt.u32.u64 %0, t; }"
        : "=r"(a) : "l"(p));
    return a;
}
__device__ __forceinline__ void mma_tf32_16x8x8(
    float& d0, float& d1, float& d2, float& d3,
    uint32_t a0, uint32_t a1, uint32_t a2, uint32_t a3,
    uint32_t b0, uint32_t b1) {
    asm volatile(
        "mma.sync.aligned.m16n8k8.row.col.f32.tf32.tf32.f32 "
        "{%0,%1,%2,%3}, {%4,%5,%6,%7}, {%8,%9}, {%0,%1,%2,%3};"
        : "+f"(d0), "+f"(d1), "+f"(d2), "+f"(d3)
        : "r"(a0), "r"(a1), "r"(a2), "r"(a3), "r"(b0), "r"(b1));
}
__device__ __forceinline__ void ldsm_x4(uint32_t& r0, uint32_t& r1,
                                        uint32_t& r2, uint32_t& r3, uint32_t a) {
    asm volatile("ldmatrix.sync.aligned.m8n8.x4.shared.b16 {%0,%1,%2,%3}, [%4];"
                 : "=r"(r0), "=r"(r1), "=r"(r2), "=r"(r3) : "r"(a));
}
#define CP16(dst, src) \
    asm volatile("cp.async.cg.shared.global [%0], [%1], 16;" :: "r"(dst), "l"(src))
#define CP_COMMIT() asm volatile("cp.async.commit_group;" ::: "memory")
#define CP_WAIT1()  asm volatile("cp.async.wait_group 1;" ::: "memory")

// Block tile: M=128 channels x N=128 pixels, K chunk 32, 8 warps (2M x 4N).
// A smem rows [m][36] floats; B smem rows [k][136] floats; 3 stages; 2 CTA/SM.
template<int KTOT, bool IS_G1>
__global__ __launch_bounds__(256, 2) void tgemm_kernel(
    const float* __restrict__ act,
    const float* __restrict__ wgt,    // pre-rounded tf32 weights
    const float* __restrict__ bias,
    const float* __restrict__ gma, const float* __restrict__ bta,
    const float* __restrict__ mnn, const float* __restrict__ vr,
    const float* __restrict__ xg,
    float* __restrict__ dst)
{
    extern __shared__ char smem[];
    constexpr int AROW = 36;                 // floats per A row (32 + pad)
    constexpr int BROW = 136;                // floats per B row (128 + pad)
    constexpr int ASTG = 128 * AROW * 4;     // 18432 B per stage
    constexpr int BSTG = 32 * BROW * 4;      // 17408 B per stage
    constexpr int AOFF = KTOT * 4;           // att_ext table first
    constexpr int BOFF = AOFF + 3 * ASTG;
    const uint32_t sb = smem_u32(smem);
    float* att_s = (float*)smem;

    const int tid = threadIdx.x;
    const int wid = tid >> 5, lane = tid & 31;
    const int g = lane >> 2, tig = lane & 3;
    const int b  = blockIdx.z;
    const int o0 = blockIdx.y * 128;
    const int p0 = blockIdx.x * 128;
    const int warpM = (wid & 1) * 64;
    const int warpN = (wid >> 1) * 32;

    const float* actb = act    + (size_t)b * C_ * HW_;
    const float* edgb = g_edge + (size_t)b * C_ * HW_;

    if (IS_G1) {
        const float* attb = g_att + b * C_;
        for (int i = tid; i < KTOT; i += 256)
            att_s[i] = (i < C_) ? attb[i] : 1.f;
    }

    // ldmatrix per-lane row offset within an A stage
    const int lrow = (lane & 7) + ((lane >> 3) & 1) * 8;
    const int lk   = (lane >> 4) * 4;
    const uint32_t a_lane_off = (uint32_t)((warpM + lrow) * AROW + lk) * 4;

    #define ISSUE_CHUNK(T)                                                        \
    {                                                                             \
        const int slot_ = (T) % 3;                                                \
        const int k0_ = (T) * 32;                                                 \
        const uint32_t ab_ = sb + AOFF + slot_ * ASTG;                            \
        const uint32_t bb_ = sb + BOFF + slot_ * BSTG;                            \
        _Pragma("unroll")                                                         \
        for (int i = 0; i < 4; i++) {                                             \
            const int ai_ = tid + i * 256;                                        \
            const int am_ = ai_ >> 3, aq_ = ai_ & 7;                              \
            const float* as_ = wgt + (size_t)(o0 + am_) * KTOT + k0_ + aq_ * 4;   \
            CP16(ab_ + (uint32_t)(am_ * AROW + aq_ * 4) * 4, as_);                \
            const int bkr_ = ai_ >> 5, bcq_ = ai_ & 31;                           \
            const int kg_ = k0_ + bkr_;                                           \
            const float* bs_;                                                     \
            if (IS_G1 && kg_ >= C_)                                               \
                bs_ = edgb + (size_t)(kg_ - C_) * HW_ + p0 + bcq_ * 4;            \
            else                                                                  \
                bs_ = actb + (size_t)kg_ * HW_ + p0 + bcq_ * 4;                   \
            CP16(bb_ + (uint32_t)(bkr_ * BROW + bcq_ * 4) * 4, bs_);              \
        }                                                                         \
    }

    float acc[4][4][4];
    #pragma unroll
    for (int i = 0; i < 4; i++)
        #pragma unroll
        for (int j = 0; j < 4; j++)
            #pragma unroll
            for (int q = 0; q < 4; q++) acc[i][j][q] = 0.f;

    const int NT = KTOT / 32;
    ISSUE_CHUNK(0); CP_COMMIT();
    ISSUE_CHUNK(1); CP_COMMIT();

    for (int t = 0; t < NT; t++) {
        CP_WAIT1();
        __syncthreads();
        if (t + 2 < NT) ISSUE_CHUNK(t + 2);
        CP_COMMIT();

        const int slot = t % 3;
        const uint32_t Aad = sb + AOFF + slot * ASTG + a_lane_off;
        const float* Br = (const float*)(smem + BOFF + slot * BSTG);
        const int kb0 = t * 32;

        #pragma unroll
        for (int kb = 0; kb < 32; kb += 8) {
            uint32_t af[4][4], bf[4][2];
            #pragma unroll
            for (int mt = 0; mt < 4; mt++)
                ldsm_x4(af[mt][0], af[mt][1], af[mt][2], af[mt][3],
                        Aad + (uint32_t)(mt * 16 * AROW + kb) * 4);
            if (IS_G1) {
                const float sa0 = att_s[kb0 + kb + tig];
                const float sa1 = att_s[kb0 + kb + tig + 4];
                #pragma unroll
                for (int nt = 0; nt < 4; nt++) {
                    const int n = warpN + nt * 8 + g;
                    bf[nt][0] = f2tf32(Br[(kb + tig) * BROW + n] * sa0);
                    bf[nt][1] = f2tf32(Br[(kb + tig + 4) * BROW + n] * sa1);
                }
            } else {
                #pragma unroll
                for (int nt = 0; nt < 4; nt++) {
                    const int n = warpN + nt * 8 + g;
                    bf[nt][0] = __float_as_uint(Br[(kb + tig) * BROW + n]);
                    bf[nt][1] = __float_as_uint(Br[(kb + tig + 4) * BROW + n]);
                }
            }
            #pragma unroll
            for (int mt = 0; mt < 4; mt++)
                #pragma unroll
                for (int nt = 0; nt < 4; nt++)
                    mma_tf32_16x8x8(acc[mt][nt][0], acc[mt][nt][1],
                                    acc[mt][nt][2], acc[mt][nt][3],
                                    af[mt][0], af[mt][1], af[mt][2], af[mt][3],
                                    bf[nt][0], bf[nt][1]);
        }
    }
    #undef ISSUE_CHUNK

    // ---- epilogue: BN(+bias)(+gate) and store ----
    const size_t bb = (size_t)b * C_ * HW_;
    #pragma unroll
    for (int mt = 0; mt < 4; mt++) {
        const int olo = o0 + warpM + mt * 16 + g;
        const int ohi = olo + 8;
        const float invlo = gma[olo] * rsqrtf(vr[olo] + EPS);
        const float addlo = bta[olo] - mnn[olo] * invlo + bias[olo] * invlo;
        const float invhi = gma[ohi] * rsqrtf(vr[ohi] + EPS);
        const float addhi = bta[ohi] - mnn[ohi] * invhi + bias[ohi] * invhi;
        #pragma unroll
        for (int nt = 0; nt < 4; nt++) {
            const int n = p0 + warpN + nt * 8 + 2 * tig;
            const size_t lo = bb + (size_t)olo * HW_ + n;
            const size_t hi = bb + (size_t)ohi * HW_ + n;
            float2 vlo, vhi;
            vlo.x = acc[mt][nt][0] * invlo + addlo;
            vlo.y = acc[mt][nt][1] * invlo + addlo;
            vhi.x = acc[mt][nt][2] * invhi + addhi;
            vhi.y = acc[mt][nt][3] * invhi + addhi;
            if (!IS_G1) {
                float2 xlo = *(const float2*)(xg + lo);
                float2 xhi = *(const float2*)(xg + hi);
                vlo.x *= xlo.x; vlo.y *= xlo.y;
                vhi.x *= xhi.x; vhi.y *= xhi.y;
            }
            *(float2*)(dst + lo) = vlo;
            *(float2*)(dst + hi) = vhi;
        }
    }
}

// ---------------- launch ----------------------------------------------------
extern "C" void kernel_launch(void* const* d_in, const int* in_sizes, int n_in,
                              void* d_out, int out_size) {
    const float* x          = (const float*)d_in[0];
    const float* edge_w     = (const float*)d_in[1];
    const float* edge_gamma = (const float*)d_in[2];
    const float* edge_beta  = (const float*)d_in[3];
    const float* edge_mean  = (const float*)d_in[4];
    const float* edge_var   = (const float*)d_in[5];
    const float* fc1_w      = (const float*)d_in[6];
    const float* fc2_w      = (const float*)d_in[7];
    const float* fusion_w   = (const float*)d_in[8];
    const float* fusion_b   = (const float*)d_in[9];
    const float* bn1_gamma  = (const float*)d_in[10];
    const float* bn1_beta   = (const float*)d_in[11];
    const float* bn1_mean   = (const float*)d_in[12];
    const float* bn1_var    = (const float*)d_in[13];
    const float* deform_w   = (const float*)d_in[14];
    const float* balance_w  = (const float*)d_in[15];
    const float* balance_b  = (const float*)d_in[16];
    const float* bn2_gamma  = (const float*)d_in[17];
    const float* bn2_beta   = (const float*)d_in[18];
    const float* bn2_mean   = (const float*)d_in[19];
    const float* bn2_var    = (const float*)d_in[20];
    float* out = (float*)d_out;

    float *pe = nullptr, *pt1 = nullptr, *pt2 = nullptr, *pw1 = nullptr, *pw2 = nullptr;
    cudaGetSymbolAddress((void**)&pe,  g_edge);
    cudaGetSymbolAddress((void**)&pt1, g_t1);
    cudaGetSymbolAddress((void**)&pt2, g_t2);
    cudaGetSymbolAddress((void**)&pw1, g_wt1);
    cudaGetSymbolAddress((void**)&pw2, g_wt2);

    // smem: att(KTOT*4) + 3*ASTG(18432) + 3*BSTG(17408)
    const int SMEM_G1 = 512 * 4 + 3 * 18432 + 3 * 17408;  // 109568
    const int SMEM_G2 = 256 * 4 + 3 * 18432 + 3 * 17408;  // 108544
    cudaFuncSetAttribute(tgemm_kernel<512, true>,
                         cudaFuncAttributeMaxDynamicSharedMemorySize, SMEM_G1);
    cudaFuncSetAttribute(tgemm_kernel<256, false>,
                         cudaFuncAttributeMaxDynamicSharedMemorySize, SMEM_G2);

    const int nplanes = B_ * C_;

    // 0) pre-round weights to tf32
    wcvt_kernel<<<(C_ * 2 * C_ + 255) / 256, 256>>>(fusion_w, balance_w);
    // 1+3) edge dwconv + BN + ReLU -> g_edge, fused spatial mean -> g_avg
    dwconv_kernel<true, true, false><<<nplanes, 256>>>(x, edge_w, pe,
                                                       edge_gamma, edge_beta,
                                                       edge_mean, edge_var);
    // 2) SE MLP -> g_att
    se_kernel<<<1, 512>>>(fc1_w, fc2_w);
    // 4) fusion 1x1 conv (tf32 mma.sync, K32, 3-stage, 2 CTA/SM) -> g_t1
    dim3 grid(HW_ / 128, C_ / 128, B_);
    tgemm_kernel<512, true><<<grid, 256, SMEM_G1>>>(
        x, pw1, fusion_b, bn1_gamma, bn1_beta, bn1_mean, bn1_var, x, pt1);
    // 5) deform (zero-offset) dwconv -> g_t2 (tf32-rounded for gemm2)
    dwconv_kernel<false, false, true><<<nplanes, 256>>>(pt1, deform_w, pt2,
                                                        nullptr, nullptr,
                                                        nullptr, nullptr);
    // 6) balance 1x1 conv + bias + BN2, gated by x -> out
    tgemm_kernel<256, false><<<grid, 256, SMEM_G2>>>(
        pt2, pw2, balance_b, bn2_gamma, bn2_beta, bn2_mean, bn2_var, x, out);
}